// round 10
// baseline (speedup 1.0000x reference)
#include <cuda_runtime.h>
#include <math.h>

// ---------------------------------------------------------------------------
// Problem constants
// ---------------------------------------------------------------------------
#define BATCH   4096
#define NTOK    64          // window size 8x8
#define CDIM    96
#define NHEADS  3
#define HD      32          // head dim
#define K4      384         // 4*C
#define MTOK    (BATCH * NTOK)               // 262144 tokens
#define SCALE   0.17677669529663687f   // 32^-0.5

// ---------------------------------------------------------------------------
// Scratch (device globals: the sanctioned alloc-free workaround)
// ---------------------------------------------------------------------------
__device__ float g_XsT[(size_t)CDIM * MTOK];          // state_x transposed
__device__ float g_XeT[(size_t)CDIM * MTOK];          // input_x transposed
__device__ float g_WsT[CDIM * K4];                    // Ws^T  [96][384]
__device__ float g_WeT[CDIM * K4];                    // We^T  [96][384]
__device__ float g_WpvT[2 * CDIM * CDIM];             // Wpv^T [192][96]
__device__ float g_WphT[2 * CDIM * CDIM];             // Wph^T [192][96]
__device__ float g_Ys [(size_t)MTOK * K4];            // state projections
__device__ float g_Ye [(size_t)MTOK * K4];            // input projections
__device__ float g_MvT[(size_t)2 * CDIM * MTOK];      // [cv | sv] transposed
__device__ float g_MhT[(size_t)2 * CDIM * MTOK];      // [ch | sh] transposed
__device__ float g_bias[4 * NHEADS * NTOK * NTOK];    // [tbl][h][64*64]

// ---------------------------------------------------------------------------
// Packed f32x2 helpers (sm_103a FFMA2/FADD2 path; full fp32 precision)
// ---------------------------------------------------------------------------
typedef unsigned long long u64;

__device__ __forceinline__ u64 pack2(float lo, float hi)
{
    u64 r;
    asm("mov.b64 %0, {%1, %2};" : "=l"(r)
        : "r"(__float_as_uint(lo)), "r"(__float_as_uint(hi)));
    return r;
}
__device__ __forceinline__ void unpack2(float& lo, float& hi, u64 v)
{
    unsigned a, b;
    asm("mov.b64 {%0, %1}, %2;" : "=r"(a), "=r"(b) : "l"(v));
    lo = __uint_as_float(a);
    hi = __uint_as_float(b);
}
__device__ __forceinline__ void fma2(u64& d, u64 a, u64 b)
{
    asm("fma.rn.f32x2 %0, %1, %2, %0;" : "+l"(d) : "l"(a), "l"(b));
}
__device__ __forceinline__ u64 add2(u64 a, u64 b)
{
    u64 r;
    asm("add.rn.f32x2 %0, %1, %2;" : "=l"(r) : "l"(a), "l"(b));
    return r;
}

// ---------------------------------------------------------------------------
// Fast exp on the FMA pipe (no MUFU). Valid for x in [-87, 0]; rel err ~2e-6.
// ---------------------------------------------------------------------------
__device__ __forceinline__ float fast_exp(float x)
{
    const float L2E   = 1.4426950408889634f;
    const float MAGIC = 12582912.0f;          // 1.5 * 2^23
    float y = x * L2E;
    float t = y + MAGIC;
    float f = y - (t - MAGIC);                // f in [-0.5, 0.5]
    int   i = __float_as_int(t) - 0x4B400000; // round(y)
    float p = 1.33335581e-3f;
    p = fmaf(p, f, 9.61804886e-3f);
    p = fmaf(p, f, 5.55041087e-2f);
    p = fmaf(p, f, 2.40226507e-1f);
    p = fmaf(p, f, 6.93147182e-1f);
    p = fmaf(p, f, 1.0f);
    return __int_as_float(__float_as_int(p) + (i << 23));
}

// ---------------------------------------------------------------------------
// cp.async helpers (16-byte)
// ---------------------------------------------------------------------------
__device__ __forceinline__ void cpa16(unsigned dst, const float* src)
{
    asm volatile("cp.async.ca.shared.global [%0], [%1], 16;"
                 :: "r"(dst), "l"(src));
}
__device__ __forceinline__ void cpa16z(unsigned dst, const float* src, int ok)
{
    asm volatile("cp.async.ca.shared.global [%0], [%1], 16, %2;"
                 :: "r"(dst), "l"(src), "r"(ok ? 16 : 0));
}
__device__ __forceinline__ void cpa_commit()
{
    asm volatile("cp.async.commit_group;");
}

// ---------------------------------------------------------------------------
// Transposes
// ---------------------------------------------------------------------------
__global__ __launch_bounds__(256)
void transpose_x(const float* __restrict__ X, float* __restrict__ Xt)
{
    __shared__ float tile[32][33];
    const int m0 = blockIdx.x * 32;
    const int k0 = blockIdx.y * 32;
    const int lx = threadIdx.x & 31;
    const int ly = threadIdx.x >> 5;     // 0..7
    #pragma unroll
    for (int i = 0; i < 4; i++)
        tile[ly + 8 * i][lx] = X[(size_t)(m0 + ly + 8 * i) * CDIM + k0 + lx];
    __syncthreads();
    #pragma unroll
    for (int i = 0; i < 4; i++)
        Xt[(size_t)(k0 + ly + 8 * i) * MTOK + m0 + lx] = tile[lx][ly + 8 * i];
}

__global__ void transpose_w(const float* __restrict__ W, float* __restrict__ Wt,
                            int Nr, int Kc)
{
    int idx = blockIdx.x * 256 + threadIdx.x;
    if (idx < Nr * Kc) {
        int n = idx / Kc, k = idx % Kc;
        Wt[(size_t)k * Nr + n] = W[idx];
    }
}

// ---------------------------------------------------------------------------
// GEMM (k-major inputs): C[M,Nn] = At[K,M]^T @ Wt[K,Nn] + bias[Nn]
// Tile 128x{128|96}, k-chunk 16, 256 threads, 8x{8|6} micro-tile, FFMA2,
// double-buffered 16B cp.async pipeline. NPAIRS=4 -> 128 cols, 3 -> 96 cols.
// Column mapping: pairs 0,1 at ty*4 ; pairs 2(,3) at 64+ty*4 (NPAIRS=4) or
// the single pair 2 at 64+ty*2 (NPAIRS=3).
// ---------------------------------------------------------------------------
#define BM 128
#define BKC 16
#define APAD 132   // 128 + 4 (132*4 = 528 B, multiple of 16)

template <int NPAIRS>
__global__ __launch_bounds__(256, 2)
void gemm_t(const float* __restrict__ At, const float* __restrict__ Wt,
            const float* __restrict__ bias, float* __restrict__ Cout,
            int K, int Nn)
{
    __shared__ float As[2][BKC][APAD];
    __shared__ float Bs[2][BKC][APAD];

    const int t     = threadIdx.x;
    const int mBase = blockIdx.x * BM;
    const int nBase = blockIdx.y * 128;
    const int kk    = t & 15;     // k within chunk
    const int rr    = t >> 4;     // 0..15
    const int tx    = t & 15;     // m micro-tile
    const int ty    = t >> 4;     // n micro-tile

    const unsigned sA = (unsigned)__cvta_generic_to_shared(&As[0][0][0]);
    const unsigned sB = (unsigned)__cvta_generic_to_shared(&Bs[0][0][0]);

    u64 acc[8][NPAIRS];
    #pragma unroll
    for (int i = 0; i < 8; i++)
        #pragma unroll
        for (int j = 0; j < NPAIRS; j++) acc[i][j] = 0ull;

    auto issue = [&](int k0, int buf) {
        const float* aRow = At + (size_t)(k0 + kk) * MTOK + mBase;
        const float* bRow = Wt + (size_t)(k0 + kk) * Nn + nBase;
        unsigned dA = sA + (unsigned)(((buf * BKC + kk) * APAD) * 4);
        unsigned dB = sB + (unsigned)(((buf * BKC + kk) * APAD) * 4);
        #pragma unroll
        for (int r = 0; r < 2; r++) {
            int g = rr * 4 + 64 * r;              // 16B group start
            cpa16(dA + g * 4, aRow + g);
            cpa16z(dB + g * 4, bRow + g, nBase + g < Nn);
        }
        cpa_commit();
    };

    const int NC = K / BKC;
    issue(0, 0);

    for (int c = 0; c < NC; c++) {
        const int buf = c & 1;
        if (c + 1 < NC) {
            issue((c + 1) * BKC, (c + 1) & 1);
            asm volatile("cp.async.wait_group 1;");
        } else {
            asm volatile("cp.async.wait_group 0;");
        }
        __syncthreads();

        const float (*Ab)[APAD] = As[buf];
        const float (*Bb)[APAD] = Bs[buf];
        #pragma unroll
        for (int q = 0; q < BKC; q++) {
            float4 a0 = *(const float4*)&Ab[q][tx * 4];
            float4 a1 = *(const float4*)&Ab[q][64 + tx * 4];
            u64 bn2[NPAIRS];
            {
                ulonglong2 bb0 = *(const ulonglong2*)&Bb[q][ty * 4];
                bn2[0] = bb0.x; bn2[1] = bb0.y;
                if (NPAIRS == 4) {
                    ulonglong2 bb1 = *(const ulonglong2*)&Bb[q][64 + ty * 4];
                    bn2[2] = bb1.x; bn2[3] = bb1.y;
                } else {
                    bn2[2] = *(const u64*)&Bb[q][64 + ty * 2];
                }
            }
            float am[8] = {a0.x, a0.y, a0.z, a0.w, a1.x, a1.y, a1.z, a1.w};
            #pragma unroll
            for (int i = 0; i < 8; i++) {
                u64 am2 = pack2(am[i], am[i]);
                #pragma unroll
                for (int j = 0; j < NPAIRS; j++)
                    fma2(acc[i][j], am2, bn2[j]);
            }
        }
        __syncthreads();
    }

    // Epilogue
    #pragma unroll
    for (int ih = 0; ih < 2; ih++) {
        #pragma unroll
        for (int i = 0; i < 4; i++) {
            int row = mBase + ih * 64 + tx * 4 + i;
            // pairs 0,1 -> cols nBase + ty*4 .. +3
            {
                int col = nBase + ty * 4;
                float4 bv = *(const float4*)&bias[col];
                float x0, x1, x2, x3;
                unpack2(x0, x1, acc[ih * 4 + i][0]);
                unpack2(x2, x3, acc[ih * 4 + i][1]);
                float4 r;
                r.x = x0 + bv.x; r.y = x1 + bv.y;
                r.z = x2 + bv.z; r.w = x3 + bv.w;
                *(float4*)&Cout[(size_t)row * Nn + col] = r;
            }
            if (NPAIRS == 4) {
                int col = nBase + 64 + ty * 4;
                float4 bv = *(const float4*)&bias[col];
                float x0, x1, x2, x3;
                unpack2(x0, x1, acc[ih * 4 + i][2]);
                unpack2(x2, x3, acc[ih * 4 + i][3]);
                float4 r;
                r.x = x0 + bv.x; r.y = x1 + bv.y;
                r.z = x2 + bv.z; r.w = x3 + bv.w;
                *(float4*)&Cout[(size_t)row * Nn + col] = r;
            } else {
                int col = nBase + 64 + ty * 2;
                float2 bv = *(const float2*)&bias[col];
                float x0, x1;
                unpack2(x0, x1, acc[ih * 4 + i][2]);
                float2 r;
                r.x = x0 + bv.x; r.y = x1 + bv.y;
                *(float2*)&Cout[(size_t)row * Nn + col] = r;
            }
        }
    }
}

// ---------------------------------------------------------------------------
// Bias pre-gather: g_bias[tbl][h][i*64+j] = tbl[rel_idx[i*64+j] * 3 + h]
// ---------------------------------------------------------------------------
__global__ void bias_gather(const float* __restrict__ tcv,
                            const float* __restrict__ tsv,
                            const float* __restrict__ tch,
                            const float* __restrict__ tsh,
                            const int*   __restrict__ rel_idx)
{
    const int tbl = blockIdx.y;
    const int h   = blockIdx.z;
    const float* T = (tbl == 0) ? tcv : (tbl == 1) ? tsv : (tbl == 2) ? tch : tsh;
    int idx = blockIdx.x * 256 + threadIdx.x;
    g_bias[(size_t)(tbl * NHEADS + h) * (NTOK * NTOK) + idx] =
        T[rel_idx[idx] * NHEADS + h];
}

// ---------------------------------------------------------------------------
// Window attention. Grid (BATCH, NHEADS, 2). 128 threads, 4 warps.
// Memory placement (smem budget -> 5 CTAs/SM):
//   K tile  : smem [64][36]          (broadcast LDS.128 in QK)
//   V rows  : warp-uniform LDG       (L1 pipe; shared by all 4 warps)
//   Q row   : registers via LDG      (read once)
//   bias    : fused into QK via float4 LDG from pre-gathered tables
//   scores  : smem [2][64][65]
// ---------------------------------------------------------------------------
#define TP 36
#define KTSZ (NTOK * TP)                       // 2304 floats
#define SP 65
#define ATTN_SMEM ((KTSZ + 2 * NTOK * SP) * sizeof(float))   // 42496 B

__global__ __launch_bounds__(128)
void attn_kernel()
{
    extern __shared__ float sm[];
    float* kt     = sm;                // [64][36]
    float* scoreS = sm + KTSZ;         // [2][64][65]

    const int b = blockIdx.x;
    const int h = blockIdx.y;
    const int z = blockIdx.z;

    const float* __restrict__ Y = z ? g_Ye : g_Ys;
    const float  sclA = z ? 1.0f  : SCALE;
    const float  sclB = z ? SCALE : SCALE * SCALE;
    float* outA = g_MvT + (size_t)((z ? CDIM : 0) + h * HD) * MTOK;
    float* outB = g_MhT + (size_t)((z ? 0 : CDIM) + h * HD) * MTOK;
    const float* bTabA = g_bias + (size_t)((z ? 1 : 0) * NHEADS + h) * (NTOK * NTOK);
    const float* bTabB = g_bias + (size_t)((z ? 2 : 3) * NHEADS + h) * (NTOK * NTOK);

    const int t    = threadIdx.x;
    const int lane = t & 31;
    const int warp = t >> 5;

    // ---- K tile into smem (coalesced fill) ----
    #pragma unroll
    for (int r = 0; r < 16; r++) {
        int i = warp * 16 + r;
        kt[i * TP + lane] = Y[(size_t)(b * NTOK + i) * K4 + h * HD + lane];
    }
    __syncthreads();

    const int   type = warp >> 1;     // 0 = A, 1 = B
    const int   half = warp & 1;      // query-row half
    const int   row  = half * 32 + lane;
    const float scl  = type ? sclB : sclA;
    float* St        = scoreS + type * NTOK * SP + row * SP;
    float* outP      = type ? outB : outA;
    const float* bRow = (type ? bTabB : bTabA) + row * NTOK;
    const float* qg   = Y + (size_t)(b * NTOK + row) * K4 + (2 + type) * CDIM + h * HD;
    const float* vg0  = Y + (size_t)(b * NTOK) * K4 + CDIM + h * HD;   // + j*K4

    // ---- q row into registers as 16 packed pairs (8 x LDG.128) ----
    u64 qr2[16];
    #pragma unroll
    for (int c = 0; c < 8; c++) {
        ulonglong2 v2 = *(const ulonglong2*)(qg + 4 * c);
        qr2[2 * c + 0] = v2.x;
        qr2[2 * c + 1] = v2.y;
    }

    // ---- scores: S[row][j] = scl * <q_row, k_j> + bias (bias fused) ----
    for (int j0 = 0; j0 < NTOK; j0 += 4) {
        float4 bv = *(const float4*)(bRow + j0);
        float bj[4] = {bv.x, bv.y, bv.z, bv.w};
        #pragma unroll
        for (int jj = 0; jj < 4; jj++) {
            const float* kj = kt + (j0 + jj) * TP;
            u64 sA = 0ull, sB = 0ull, sC = 0ull, sD = 0ull;
            #pragma unroll
            for (int c = 0; c < 4; c++) {
                ulonglong2 k0 = *(const ulonglong2*)(kj + 8 * c);       // bcast
                ulonglong2 k1 = *(const ulonglong2*)(kj + 8 * c + 4);
                fma2(sA, qr2[4 * c + 0], k0.x);
                fma2(sB, qr2[4 * c + 1], k0.y);
                fma2(sC, qr2[4 * c + 2], k1.x);
                fma2(sD, qr2[4 * c + 3], k1.y);
            }
            u64 sT = add2(add2(sA, sB), add2(sC, sD));
            float lo, hi;
            unpack2(lo, hi, sT);
            St[j0 + jj] = fmaf(scl, lo + hi, bj[jj]);
        }
    }

    // ---- softmax over my row (FMA-pipe exp; normalization deferred) ----
    float mx = -1e30f;
    #pragma unroll 8
    for (int j = 0; j < NTOK; j++) mx = fmaxf(mx, St[j]);
    float sum = 0.f;
    #pragma unroll 8
    for (int j = 0; j < NTOK; j++) {
        float e = fast_exp(St[j] - mx);
        St[j] = e;
        sum += e;
    }
    const float inv = 1.f / sum;

    // ---- PV: V rows streamed via warp-uniform LDG (L1 pipe) ----
    u64 ou2[16];
    #pragma unroll
    for (int c = 0; c < 16; c++) ou2[c] = 0ull;
    #pragma unroll 4
    for (int j = 0; j < NTOK; j++) {
        const float p = St[j];
        const u64 p2 = pack2(p, p);
        const float* vj = vg0 + (size_t)j * K4;
        #pragma unroll
        for (int c = 0; c < 8; c++) {
            ulonglong2 vv = *(const ulonglong2*)(vj + 4 * c);   // uniform
            fma2(ou2[2 * c + 0], p2, vv.x);
            fma2(ou2[2 * c + 1], p2, vv.y);
        }
    }

    // ---- transposed stores: dim-major, lanes = consecutive tokens ----
    float* op = outP + (size_t)b * NTOK + row;
    #pragma unroll
    for (int c = 0; c < 16; c++) {
        float x0, x1;
        unpack2(x0, x1, ou2[c]);
        op[(size_t)(2 * c + 0) * MTOK] = x0 * inv;
        op[(size_t)(2 * c + 1) * MTOK] = x1 * inv;
    }
}

// ---------------------------------------------------------------------------
// Launch
// ---------------------------------------------------------------------------
extern "C" void kernel_launch(void* const* d_in, const int* in_sizes, int n_in,
                              void* d_out, int out_size)
{
    const float* input_x = (const float*)d_in[0];
    const float* state_x = (const float*)d_in[1];
    const float* Ws      = (const float*)d_in[2];
    const float* bs      = (const float*)d_in[3];
    const float* We      = (const float*)d_in[4];
    const float* be      = (const float*)d_in[5];
    const float* tcv     = (const float*)d_in[6];
    const float* tsv     = (const float*)d_in[7];
    const float* tch     = (const float*)d_in[8];
    const float* tsh     = (const float*)d_in[9];
    const float* Wpv     = (const float*)d_in[10];
    const float* bpv     = (const float*)d_in[11];
    const float* Wph     = (const float*)d_in[12];
    const float* bph     = (const float*)d_in[13];
    const int*   rel_idx = (const int*)d_in[14];

    float* out   = (float*)d_out;
    float* state = out + (size_t)MTOK * CDIM;

    float *pXsT, *pXeT, *pWsT, *pWeT, *pWpvT, *pWphT, *pYs, *pYe, *pMvT, *pMhT;
    cudaGetSymbolAddress((void**)&pXsT,  g_XsT);
    cudaGetSymbolAddress((void**)&pXeT,  g_XeT);
    cudaGetSymbolAddress((void**)&pWsT,  g_WsT);
    cudaGetSymbolAddress((void**)&pWeT,  g_WeT);
    cudaGetSymbolAddress((void**)&pWpvT, g_WpvT);
    cudaGetSymbolAddress((void**)&pWphT, g_WphT);
    cudaGetSymbolAddress((void**)&pYs,   g_Ys);
    cudaGetSymbolAddress((void**)&pYe,   g_Ye);
    cudaGetSymbolAddress((void**)&pMvT,  g_MvT);
    cudaGetSymbolAddress((void**)&pMhT,  g_MhT);

    cudaFuncSetAttribute(attn_kernel,
                         cudaFuncAttributeMaxDynamicSharedMemorySize,
                         (int)ATTN_SMEM);

    // Pre-pass: transposes + bias gather (small)
    {
        dim3 gx(MTOK / 32, CDIM / 32);
        transpose_x<<<gx, 256>>>(state_x, pXsT);
        transpose_x<<<gx, 256>>>(input_x, pXeT);
        transpose_w<<<(K4 * CDIM + 255) / 256, 256>>>(Ws, pWsT, K4, CDIM);
        transpose_w<<<(K4 * CDIM + 255) / 256, 256>>>(We, pWeT, K4, CDIM);
        transpose_w<<<(CDIM * 2 * CDIM + 255) / 256, 256>>>(Wpv, pWpvT, CDIM, 2 * CDIM);
        transpose_w<<<(CDIM * 2 * CDIM + 255) / 256, 256>>>(Wph, pWphT, CDIM, 2 * CDIM);
        dim3 gb(NTOK * NTOK / 256, 4, NHEADS);
        bias_gather<<<gb, 256>>>(tcv, tsv, tch, tsh, rel_idx);
    }

    // Stage 1: projections  Y = X @ W^T + b   -> [M, 384]
    {
        dim3 grid(MTOK / BM, K4 / 128);     // (2048, 3)
        gemm_t<4><<<grid, 256>>>(pXsT, pWsT, bs, pYs, CDIM, K4);
        gemm_t<4><<<grid, 256>>>(pXeT, pWeT, be, pYe, CDIM, K4);
    }

    // Stage 2: 4 window attentions per (b, h) -> transposed merge buffers
    {
        dim3 grid(BATCH, NHEADS, 2);
        attn_kernel<<<grid, 128, ATTN_SMEM>>>();
    }

    // Stage 3: output projections (96 cols exactly; concat free via K-halves)
    {
        dim3 grid(MTOK / BM, 1);
        gemm_t<3><<<grid, 256>>>(pMvT, pWpvT, bpv, out,   2 * CDIM, CDIM);
        gemm_t<3><<<grid, 256>>>(pMhT, pWphT, bph, state, 2 * CDIM, CDIM);
    }
}

// round 11
// speedup vs baseline: 1.4051x; 1.4051x over previous
#include <cuda_runtime.h>
#include <math.h>

// ---------------------------------------------------------------------------
// Problem constants
// ---------------------------------------------------------------------------
#define BATCH   4096
#define NTOK    64          // window size 8x8
#define CDIM    96
#define NHEADS  3
#define HD      32          // head dim
#define K4      384         // 4*C
#define MTOK    (BATCH * NTOK)               // 262144 tokens
#define SCALE   0.17677669529663687f   // 32^-0.5

// ---------------------------------------------------------------------------
// Scratch (device globals: the sanctioned alloc-free workaround)
// ---------------------------------------------------------------------------
__device__ float g_XsT[(size_t)CDIM * MTOK];          // state_x transposed
__device__ float g_XeT[(size_t)CDIM * MTOK];          // input_x transposed
__device__ float g_WsT[CDIM * K4];                    // Ws^T  [96][384]
__device__ float g_WeT[CDIM * K4];                    // We^T  [96][384]
__device__ float g_WpvT[2 * CDIM * CDIM];             // Wpv^T [192][96]
__device__ float g_WphT[2 * CDIM * CDIM];             // Wph^T [192][96]
__device__ float g_Ys [(size_t)MTOK * K4];            // state projections
__device__ float g_Ye [(size_t)MTOK * K4];            // input projections
__device__ float g_MvT[(size_t)2 * CDIM * MTOK];      // [cv | sv] transposed
__device__ float g_MhT[(size_t)2 * CDIM * MTOK];      // [ch | sh] transposed
__device__ float g_biasT[4 * NHEADS * NTOK * NTOK];   // [tbl][h][j*64+i]

// ---------------------------------------------------------------------------
// Packed f32x2 helpers (sm_103a FFMA2/FADD2 path; full fp32 precision)
// ---------------------------------------------------------------------------
typedef unsigned long long u64;

__device__ __forceinline__ u64 pack2(float lo, float hi)
{
    u64 r;
    asm("mov.b64 %0, {%1, %2};" : "=l"(r)
        : "r"(__float_as_uint(lo)), "r"(__float_as_uint(hi)));
    return r;
}
__device__ __forceinline__ void unpack2(float& lo, float& hi, u64 v)
{
    unsigned a, b;
    asm("mov.b64 {%0, %1}, %2;" : "=r"(a), "=r"(b) : "l"(v));
    lo = __uint_as_float(a);
    hi = __uint_as_float(b);
}
__device__ __forceinline__ void fma2(u64& d, u64 a, u64 b)
{
    asm("fma.rn.f32x2 %0, %1, %2, %0;" : "+l"(d) : "l"(a), "l"(b));
}
__device__ __forceinline__ u64 add2(u64 a, u64 b)
{
    u64 r;
    asm("add.rn.f32x2 %0, %1, %2;" : "=l"(r) : "l"(a), "l"(b));
    return r;
}

// ---------------------------------------------------------------------------
// Fast exp on the FMA pipe (no MUFU). Valid for x in [-87, 0]; rel err ~2e-6.
// ---------------------------------------------------------------------------
__device__ __forceinline__ float fast_exp(float x)
{
    const float L2E   = 1.4426950408889634f;
    const float MAGIC = 12582912.0f;          // 1.5 * 2^23
    float y = x * L2E;
    float t = y + MAGIC;
    float f = y - (t - MAGIC);                // f in [-0.5, 0.5]
    int   i = __float_as_int(t) - 0x4B400000; // round(y)
    float p = 1.33335581e-3f;
    p = fmaf(p, f, 9.61804886e-3f);
    p = fmaf(p, f, 5.55041087e-2f);
    p = fmaf(p, f, 2.40226507e-1f);
    p = fmaf(p, f, 6.93147182e-1f);
    p = fmaf(p, f, 1.0f);
    return __int_as_float(__float_as_int(p) + (i << 23));
}

// ---------------------------------------------------------------------------
// cp.async helpers (16-byte)
// ---------------------------------------------------------------------------
__device__ __forceinline__ void cpa16(unsigned dst, const float* src)
{
    asm volatile("cp.async.ca.shared.global [%0], [%1], 16;"
                 :: "r"(dst), "l"(src));
}
__device__ __forceinline__ void cpa16z(unsigned dst, const float* src, int ok)
{
    asm volatile("cp.async.ca.shared.global [%0], [%1], 16, %2;"
                 :: "r"(dst), "l"(src), "r"(ok ? 16 : 0));
}
__device__ __forceinline__ void cpa_commit()
{
    asm volatile("cp.async.commit_group;");
}

// ---------------------------------------------------------------------------
// Transposes
// ---------------------------------------------------------------------------
__global__ __launch_bounds__(256)
void transpose_x(const float* __restrict__ X, float* __restrict__ Xt)
{
    __shared__ float tile[32][33];
    const int m0 = blockIdx.x * 32;
    const int k0 = blockIdx.y * 32;
    const int lx = threadIdx.x & 31;
    const int ly = threadIdx.x >> 5;     // 0..7
    #pragma unroll
    for (int i = 0; i < 4; i++)
        tile[ly + 8 * i][lx] = X[(size_t)(m0 + ly + 8 * i) * CDIM + k0 + lx];
    __syncthreads();
    #pragma unroll
    for (int i = 0; i < 4; i++)
        Xt[(size_t)(k0 + ly + 8 * i) * MTOK + m0 + lx] = tile[lx][ly + 8 * i];
}

__global__ void transpose_w(const float* __restrict__ W, float* __restrict__ Wt,
                            int Nr, int Kc)
{
    int idx = blockIdx.x * 256 + threadIdx.x;
    if (idx < Nr * Kc) {
        int n = idx / Kc, k = idx % Kc;
        Wt[(size_t)k * Nr + n] = W[idx];
    }
}

// ---------------------------------------------------------------------------
// GEMM (k-major inputs): C[M,Nn] = At[K,M]^T @ Wt[K,Nn] + bias[Nn]
// Tile 128x{128|96}, k-chunk 16, 256 threads, 8x{8|6} micro-tile, FFMA2,
// double-buffered 16B cp.async pipeline. NPAIRS=4 -> 128 cols, 3 -> 96 cols.
// ---------------------------------------------------------------------------
#define BM 128
#define BKC 16
#define APAD 132   // 128 + 4 (132*4 = 528 B, multiple of 16)

template <int NPAIRS>
__global__ __launch_bounds__(256, 2)
void gemm_t(const float* __restrict__ At, const float* __restrict__ Wt,
            const float* __restrict__ bias, float* __restrict__ Cout,
            int K, int Nn)
{
    __shared__ float As[2][BKC][APAD];
    __shared__ float Bs[2][BKC][APAD];

    const int t     = threadIdx.x;
    const int mBase = blockIdx.x * BM;
    const int nBase = blockIdx.y * 128;
    const int kk    = t & 15;     // k within chunk
    const int rr    = t >> 4;     // 0..15
    const int tx    = t & 15;     // m micro-tile
    const int ty    = t >> 4;     // n micro-tile

    const unsigned sA = (unsigned)__cvta_generic_to_shared(&As[0][0][0]);
    const unsigned sB = (unsigned)__cvta_generic_to_shared(&Bs[0][0][0]);

    u64 acc[8][NPAIRS];
    #pragma unroll
    for (int i = 0; i < 8; i++)
        #pragma unroll
        for (int j = 0; j < NPAIRS; j++) acc[i][j] = 0ull;

    auto issue = [&](int k0, int buf) {
        const float* aRow = At + (size_t)(k0 + kk) * MTOK + mBase;
        const float* bRow = Wt + (size_t)(k0 + kk) * Nn + nBase;
        unsigned dA = sA + (unsigned)(((buf * BKC + kk) * APAD) * 4);
        unsigned dB = sB + (unsigned)(((buf * BKC + kk) * APAD) * 4);
        #pragma unroll
        for (int r = 0; r < 2; r++) {
            int g = rr * 4 + 64 * r;              // 16B group start
            cpa16(dA + g * 4, aRow + g);
            cpa16z(dB + g * 4, bRow + g, nBase + g < Nn);
        }
        cpa_commit();
    };

    const int NC = K / BKC;
    issue(0, 0);

    for (int c = 0; c < NC; c++) {
        const int buf = c & 1;
        if (c + 1 < NC) {
            issue((c + 1) * BKC, (c + 1) & 1);
            asm volatile("cp.async.wait_group 1;");
        } else {
            asm volatile("cp.async.wait_group 0;");
        }
        __syncthreads();

        const float (*Ab)[APAD] = As[buf];
        const float (*Bb)[APAD] = Bs[buf];
        #pragma unroll
        for (int q = 0; q < BKC; q++) {
            float4 a0 = *(const float4*)&Ab[q][tx * 4];
            float4 a1 = *(const float4*)&Ab[q][64 + tx * 4];
            u64 bn2[NPAIRS];
            {
                ulonglong2 bb0 = *(const ulonglong2*)&Bb[q][ty * 4];
                bn2[0] = bb0.x; bn2[1] = bb0.y;
                if (NPAIRS == 4) {
                    ulonglong2 bb1 = *(const ulonglong2*)&Bb[q][64 + ty * 4];
                    bn2[2] = bb1.x; bn2[3] = bb1.y;
                } else {
                    bn2[2] = *(const u64*)&Bb[q][64 + ty * 2];
                }
            }
            float am[8] = {a0.x, a0.y, a0.z, a0.w, a1.x, a1.y, a1.z, a1.w};
            #pragma unroll
            for (int i = 0; i < 8; i++) {
                u64 am2 = pack2(am[i], am[i]);
                #pragma unroll
                for (int j = 0; j < NPAIRS; j++)
                    fma2(acc[i][j], am2, bn2[j]);
            }
        }
        __syncthreads();
    }

    // Epilogue
    #pragma unroll
    for (int ih = 0; ih < 2; ih++) {
        #pragma unroll
        for (int i = 0; i < 4; i++) {
            int row = mBase + ih * 64 + tx * 4 + i;
            {
                int col = nBase + ty * 4;
                float4 bv = *(const float4*)&bias[col];
                float x0, x1, x2, x3;
                unpack2(x0, x1, acc[ih * 4 + i][0]);
                unpack2(x2, x3, acc[ih * 4 + i][1]);
                float4 r;
                r.x = x0 + bv.x; r.y = x1 + bv.y;
                r.z = x2 + bv.z; r.w = x3 + bv.w;
                *(float4*)&Cout[(size_t)row * Nn + col] = r;
            }
            if (NPAIRS == 4) {
                int col = nBase + 64 + ty * 4;
                float4 bv = *(const float4*)&bias[col];
                float x0, x1, x2, x3;
                unpack2(x0, x1, acc[ih * 4 + i][2]);
                unpack2(x2, x3, acc[ih * 4 + i][3]);
                float4 r;
                r.x = x0 + bv.x; r.y = x1 + bv.y;
                r.z = x2 + bv.z; r.w = x3 + bv.w;
                *(float4*)&Cout[(size_t)row * Nn + col] = r;
            } else {
                int col = nBase + 64 + ty * 2;
                float2 bv = *(const float2*)&bias[col];
                float x0, x1;
                unpack2(x0, x1, acc[ih * 4 + i][2]);
                float2 r;
                r.x = x0 + bv.x; r.y = x1 + bv.y;
                *(float2*)&Cout[(size_t)row * Nn + col] = r;
            }
        }
    }
}

// ---------------------------------------------------------------------------
// Bias pre-gather, TRANSPOSED: g_biasT[tbl][h][j*64+i] = tbl[rel_idx[i*64+j]*3+h]
// (so a warp reading fixed j across i is a coalesced LDG)
// ---------------------------------------------------------------------------
__global__ void bias_gather(const float* __restrict__ tcv,
                            const float* __restrict__ tsv,
                            const float* __restrict__ tch,
                            const float* __restrict__ tsh,
                            const int*   __restrict__ rel_idx)
{
    const int tbl = blockIdx.y;
    const int h   = blockIdx.z;
    const float* T = (tbl == 0) ? tcv : (tbl == 1) ? tsv : (tbl == 2) ? tch : tsh;
    int idx = blockIdx.x * 256 + threadIdx.x;      // idx = i*64 + j
    int i = idx >> 6, j = idx & 63;
    g_biasT[(size_t)(tbl * NHEADS + h) * (NTOK * NTOK) + j * NTOK + i] =
        T[rel_idx[idx] * NHEADS + h];
}

// ---------------------------------------------------------------------------
// Window attention. Grid (BATCH, NHEADS, 2). 128 threads, 4 warps.
//   z = 0: source = Ys  -> typeA = attn_cv (scale),  typeB = attn_sh (scale^2)
//   z = 1: source = Ye  -> typeA = attn_sv (1.0),    typeB = attn_ch (scale)
// R8 memory placement (4 smem tiles, broadcast LDS) + scores in REGISTERS:
//   - lane owns one query row; its 64 scores live in registers (full unroll)
//   - bias read transposed: one coalesced LDG.32 per j, fused into QK
//   - softmax entirely in registers; smem = 36.9 KB -> 4 CTAs/SM (16 warps)
// ---------------------------------------------------------------------------
#define TP 36                                  // tile pitch (floats)
#define TSZ (NTOK * TP)                        // 2304 floats per tile

__global__ __launch_bounds__(128, 4)
void attn_kernel()
{
    __shared__ float tiles[4 * TSZ];           // k, v, qA, qB

    const int b = blockIdx.x;
    const int h = blockIdx.y;
    const int z = blockIdx.z;

    const float* __restrict__ Y = z ? g_Ye : g_Ys;
    const float  sclA = z ? 1.0f  : SCALE;
    const float  sclB = z ? SCALE : SCALE * SCALE;
    float* outA = g_MvT + (size_t)((z ? CDIM : 0) + h * HD) * MTOK;
    float* outB = g_MhT + (size_t)((z ? 0 : CDIM) + h * HD) * MTOK;
    const float* bTA = g_biasT + (size_t)((z ? 1 : 0) * NHEADS + h) * (NTOK * NTOK);
    const float* bTB = g_biasT + (size_t)((z ? 2 : 3) * NHEADS + h) * (NTOK * NTOK);

    const int t    = threadIdx.x;
    const int lane = t & 31;
    const int warp = t >> 5;

    // ---- load 4 projection tiles [64][32] (cols j4*96 + h*32 + lane) ----
    #pragma unroll
    for (int j4 = 0; j4 < 4; j4++) {
        #pragma unroll
        for (int r = 0; r < 16; r++) {
            int i = warp * 16 + r;
            tiles[j4 * TSZ + i * TP + lane] =
                Y[(size_t)(b * NTOK + i) * K4 + j4 * CDIM + h * HD + lane];
        }
    }
    __syncthreads();

    const int   type = warp >> 1;     // 0 = A, 1 = B
    const int   half = warp & 1;      // query-row half
    const int   row  = half * 32 + lane;
    const float scl  = type ? sclB : sclA;
    const float* Kt  = tiles;                 // keys
    const float* Vt  = tiles + TSZ;           // values
    const float* qp  = tiles + (2 + type) * TSZ + row * TP;
    const float* bT  = (type ? bTB : bTA) + row;   // + j*64
    float* outP      = type ? outB : outA;

    // ---- q row into registers as 16 packed pairs (conflict-free LDS.128) ----
    u64 qr2[16];
    #pragma unroll
    for (int c = 0; c < 8; c++) {
        ulonglong2 v2 = *(const ulonglong2*)(qp + 4 * c);
        qr2[2 * c + 0] = v2.x;
        qr2[2 * c + 1] = v2.y;
    }

    // ---- scores in registers: sc[j] = scl * <q_row, k_j> + bias[j][row] ----
    float sc[NTOK];
    #pragma unroll
    for (int j = 0; j < NTOK; j++) {
        const float* kj = Kt + j * TP;
        float bj = bT[j * NTOK];                     // coalesced LDG.32
        u64 sA = 0ull, sB = 0ull, sC = 0ull, sD = 0ull;
        #pragma unroll
        for (int c = 0; c < 4; c++) {
            ulonglong2 k0 = *(const ulonglong2*)(kj + 8 * c);       // bcast
            ulonglong2 k1 = *(const ulonglong2*)(kj + 8 * c + 4);
            fma2(sA, qr2[4 * c + 0], k0.x);
            fma2(sB, qr2[4 * c + 1], k0.y);
            fma2(sC, qr2[4 * c + 2], k1.x);
            fma2(sD, qr2[4 * c + 3], k1.y);
        }
        u64 sT = add2(add2(sA, sB), add2(sC, sD));
        float lo, hi;
        unpack2(lo, hi, sT);
        sc[j] = fmaf(scl, lo + hi, bj);
    }

    // ---- softmax in registers (FMA-pipe exp; normalization deferred) ----
    float mx = -1e30f;
    #pragma unroll
    for (int j = 0; j < NTOK; j++) mx = fmaxf(mx, sc[j]);
    float sum = 0.f;
    #pragma unroll
    for (int j = 0; j < NTOK; j++) {
        float e = fast_exp(sc[j] - mx);
        sc[j] = e;
        sum += e;
    }
    const float inv = 1.f / sum;

    // ---- PV: ou2[c] += p2 * v_pair (V broadcast from smem) ----
    u64 ou2[16];
    #pragma unroll
    for (int c = 0; c < 16; c++) ou2[c] = 0ull;
    #pragma unroll
    for (int j = 0; j < NTOK; j++) {
        const u64 p2 = pack2(sc[j], sc[j]);
        const float* vj = Vt + j * TP;
        #pragma unroll
        for (int c = 0; c < 8; c++) {
            ulonglong2 vv = *(const ulonglong2*)(vj + 4 * c);   // broadcast
            fma2(ou2[2 * c + 0], p2, vv.x);
            fma2(ou2[2 * c + 1], p2, vv.y);
        }
    }

    // ---- transposed stores: dim-major, lanes = consecutive tokens ----
    float* op = outP + (size_t)b * NTOK + row;
    #pragma unroll
    for (int c = 0; c < 16; c++) {
        float x0, x1;
        unpack2(x0, x1, ou2[c]);
        op[(size_t)(2 * c + 0) * MTOK] = x0 * inv;
        op[(size_t)(2 * c + 1) * MTOK] = x1 * inv;
    }
}

// ---------------------------------------------------------------------------
// Launch
// ---------------------------------------------------------------------------
extern "C" void kernel_launch(void* const* d_in, const int* in_sizes, int n_in,
                              void* d_out, int out_size)
{
    const float* input_x = (const float*)d_in[0];
    const float* state_x = (const float*)d_in[1];
    const float* Ws      = (const float*)d_in[2];
    const float* bs      = (const float*)d_in[3];
    const float* We      = (const float*)d_in[4];
    const float* be      = (const float*)d_in[5];
    const float* tcv     = (const float*)d_in[6];
    const float* tsv     = (const float*)d_in[7];
    const float* tch     = (const float*)d_in[8];
    const float* tsh     = (const float*)d_in[9];
    const float* Wpv     = (const float*)d_in[10];
    const float* bpv     = (const float*)d_in[11];
    const float* Wph     = (const float*)d_in[12];
    const float* bph     = (const float*)d_in[13];
    const int*   rel_idx = (const int*)d_in[14];

    float* out   = (float*)d_out;
    float* state = out + (size_t)MTOK * CDIM;

    float *pXsT, *pXeT, *pWsT, *pWeT, *pWpvT, *pWphT, *pYs, *pYe, *pMvT, *pMhT;
    cudaGetSymbolAddress((void**)&pXsT,  g_XsT);
    cudaGetSymbolAddress((void**)&pXeT,  g_XeT);
    cudaGetSymbolAddress((void**)&pWsT,  g_WsT);
    cudaGetSymbolAddress((void**)&pWeT,  g_WeT);
    cudaGetSymbolAddress((void**)&pWpvT, g_WpvT);
    cudaGetSymbolAddress((void**)&pWphT, g_WphT);
    cudaGetSymbolAddress((void**)&pYs,   g_Ys);
    cudaGetSymbolAddress((void**)&pYe,   g_Ye);
    cudaGetSymbolAddress((void**)&pMvT,  g_MvT);
    cudaGetSymbolAddress((void**)&pMhT,  g_MhT);

    // Pre-pass: transposes + bias gather (small)
    {
        dim3 gx(MTOK / 32, CDIM / 32);
        transpose_x<<<gx, 256>>>(state_x, pXsT);
        transpose_x<<<gx, 256>>>(input_x, pXeT);
        transpose_w<<<(K4 * CDIM + 255) / 256, 256>>>(Ws, pWsT, K4, CDIM);
        transpose_w<<<(K4 * CDIM + 255) / 256, 256>>>(We, pWeT, K4, CDIM);
        transpose_w<<<(CDIM * 2 * CDIM + 255) / 256, 256>>>(Wpv, pWpvT, CDIM, 2 * CDIM);
        transpose_w<<<(CDIM * 2 * CDIM + 255) / 256, 256>>>(Wph, pWphT, CDIM, 2 * CDIM);
        dim3 gb(NTOK * NTOK / 256, 4, NHEADS);
        bias_gather<<<gb, 256>>>(tcv, tsv, tch, tsh, rel_idx);
    }

    // Stage 1: projections  Y = X @ W^T + b   -> [M, 384]
    {
        dim3 grid(MTOK / BM, K4 / 128);     // (2048, 3)
        gemm_t<4><<<grid, 256>>>(pXsT, pWsT, bs, pYs, CDIM, K4);
        gemm_t<4><<<grid, 256>>>(pXeT, pWeT, be, pYe, CDIM, K4);
    }

    // Stage 2: 4 window attentions per (b, h) -> transposed merge buffers
    {
        dim3 grid(BATCH, NHEADS, 2);
        attn_kernel<<<grid, 128>>>();
    }

    // Stage 3: output projections (96 cols exactly; concat free via K-halves)
    {
        dim3 grid(MTOK / BM, 1);
        gemm_t<3><<<grid, 256>>>(pMvT, pWpvT, bpv, out,   2 * CDIM, CDIM);
        gemm_t<3><<<grid, 256>>>(pMhT, pWphT, bph, state, 2 * CDIM, CDIM);
    }
}

// round 13
// speedup vs baseline: 1.8413x; 1.3105x over previous
#include <cuda_runtime.h>
#include <cuda_bf16.h>
#include <math.h>

// ---------------------------------------------------------------------------
// Problem constants
// ---------------------------------------------------------------------------
#define BATCH   4096
#define NTOK    64
#define CDIM    96
#define NHEADS  3
#define HD      32
#define K4      384
#define MTOK    (BATCH * NTOK)               // 262144 tokens
#define SCALE   0.17677669529663687f

// ---------------------------------------------------------------------------
// Scratch (device globals)
// ---------------------------------------------------------------------------
__device__ __nv_bfloat16 g_Xs_hi[(size_t)MTOK * CDIM];
__device__ __nv_bfloat16 g_Xs_lo[(size_t)MTOK * CDIM];
__device__ __nv_bfloat16 g_Xe_hi[(size_t)MTOK * CDIM];
__device__ __nv_bfloat16 g_Xe_lo[(size_t)MTOK * CDIM];
__device__ __nv_bfloat16 g_Ws_hi[K4 * CDIM];
__device__ __nv_bfloat16 g_Ws_lo[K4 * CDIM];
__device__ __nv_bfloat16 g_We_hi[K4 * CDIM];
__device__ __nv_bfloat16 g_We_lo[K4 * CDIM];
__device__ float g_WpvT[2 * CDIM * CDIM];             // Wpv^T [192][96]
__device__ float g_WphT[2 * CDIM * CDIM];             // Wph^T [192][96]
__device__ float g_Ys [(size_t)MTOK * K4];            // row-major [token][384]
__device__ float g_Ye [(size_t)MTOK * K4];
__device__ float g_MvT[(size_t)2 * CDIM * MTOK];      // [cv | sv] dim-major
__device__ float g_MhT[(size_t)2 * CDIM * MTOK];      // [ch | sh] dim-major
__device__ float g_biasT[4 * NHEADS * NTOK * NTOK];   // [tbl][h][j*64+i]

// ---------------------------------------------------------------------------
// Packed f32x2 helpers
// ---------------------------------------------------------------------------
typedef unsigned long long u64;

__device__ __forceinline__ u64 pack2(float lo, float hi)
{
    u64 r;
    asm("mov.b64 %0, {%1, %2};" : "=l"(r)
        : "r"(__float_as_uint(lo)), "r"(__float_as_uint(hi)));
    return r;
}
__device__ __forceinline__ void unpack2(float& lo, float& hi, u64 v)
{
    unsigned a, b;
    asm("mov.b64 {%0, %1}, %2;" : "=r"(a), "=r"(b) : "l"(v));
    lo = __uint_as_float(a);
    hi = __uint_as_float(b);
}
__device__ __forceinline__ void fma2(u64& d, u64 a, u64 b)
{
    asm("fma.rn.f32x2 %0, %1, %2, %0;" : "+l"(d) : "l"(a), "l"(b));
}
__device__ __forceinline__ u64 add2(u64 a, u64 b)
{
    u64 r;
    asm("add.rn.f32x2 %0, %1, %2;" : "=l"(r) : "l"(a), "l"(b));
    return r;
}

__device__ __forceinline__ float fast_exp(float x)
{
    const float L2E   = 1.4426950408889634f;
    const float MAGIC = 12582912.0f;
    float y = x * L2E;
    float t = y + MAGIC;
    float f = y - (t - MAGIC);
    int   i = __float_as_int(t) - 0x4B400000;
    float p = 1.33335581e-3f;
    p = fmaf(p, f, 9.61804886e-3f);
    p = fmaf(p, f, 5.55041087e-2f);
    p = fmaf(p, f, 2.40226507e-1f);
    p = fmaf(p, f, 6.93147182e-1f);
    p = fmaf(p, f, 1.0f);
    return __int_as_float(__float_as_int(p) + (i << 23));
}

// ---------------------------------------------------------------------------
// cp.async helpers
// ---------------------------------------------------------------------------
__device__ __forceinline__ void cpa16(unsigned dst, const void* src)
{
    asm volatile("cp.async.ca.shared.global [%0], [%1], 16;"
                 :: "r"(dst), "l"(src));
}
__device__ __forceinline__ void cpa16z(unsigned dst, const void* src, int ok)
{
    asm volatile("cp.async.ca.shared.global [%0], [%1], 16, %2;"
                 :: "r"(dst), "l"(src), "r"(ok ? 16 : 0));
}
__device__ __forceinline__ void cpa_commit()
{
    asm volatile("cp.async.commit_group;");
}

// ---------------------------------------------------------------------------
// mma.sync / ldmatrix (baseline sm_80 PTX — compiles under sm_103 target)
// ---------------------------------------------------------------------------
__device__ __forceinline__ void ldsm4(unsigned* r, unsigned addr)
{
    asm volatile("ldmatrix.sync.aligned.m8n8.x4.shared.b16 {%0,%1,%2,%3}, [%4];"
                 : "=r"(r[0]), "=r"(r[1]), "=r"(r[2]), "=r"(r[3]) : "r"(addr));
}
__device__ __forceinline__ void mma16816(float* d, const unsigned* a,
                                         unsigned b0, unsigned b1)
{
    asm volatile(
        "mma.sync.aligned.m16n8k16.row.col.f32.bf16.bf16.f32 "
        "{%0,%1,%2,%3}, {%4,%5,%6,%7}, {%8,%9}, {%0,%1,%2,%3};"
        : "+f"(d[0]), "+f"(d[1]), "+f"(d[2]), "+f"(d[3])
        : "r"(a[0]), "r"(a[1]), "r"(a[2]), "r"(a[3]), "r"(b0), "r"(b1));
}

// ---------------------------------------------------------------------------
// Prepass kernels
// ---------------------------------------------------------------------------
__global__ void bias_gather(const float* __restrict__ tcv,
                            const float* __restrict__ tsv,
                            const float* __restrict__ tch,
                            const float* __restrict__ tsh,
                            const int*   __restrict__ rel_idx)
{
    const int tbl = blockIdx.y;
    const int h   = blockIdx.z;
    const float* T = (tbl == 0) ? tcv : (tbl == 1) ? tsv : (tbl == 2) ? tch : tsh;
    int idx = blockIdx.x * 256 + threadIdx.x;      // idx = i*64 + j
    int i = idx >> 6, j = idx & 63;
    g_biasT[(size_t)(tbl * NHEADS + h) * (NTOK * NTOK) + j * NTOK + i] =
        T[rel_idx[idx] * NHEADS + h];
}

__global__ __launch_bounds__(256)
void convert_split(const float* __restrict__ X,
                   __nv_bfloat16* __restrict__ hi,
                   __nv_bfloat16* __restrict__ lo, size_t n)
{
    size_t idx = ((size_t)blockIdx.x * 256 + threadIdx.x) * 4;
    if (idx >= n) return;
    float4 v = *(const float4*)(X + idx);
    float xs[4] = {v.x, v.y, v.z, v.w};
    __nv_bfloat16 h4[4], l4[4];
    #pragma unroll
    for (int c = 0; c < 4; c++) {
        __nv_bfloat16 hb = __float2bfloat16(xs[c]);
        h4[c] = hb;
        l4[c] = __float2bfloat16(xs[c] - __bfloat162float(hb));
    }
    *(ulonglong1*)(hi + idx) = *(ulonglong1*)h4;
    *(ulonglong1*)(lo + idx) = *(ulonglong1*)l4;
}

__global__ void transpose_w2(const float* __restrict__ Wpv,
                             const float* __restrict__ Wph)
{
    const float* W = blockIdx.y ? Wph : Wpv;
    float* Wt      = blockIdx.y ? g_WphT : g_WpvT;
    int idx = blockIdx.x * 256 + threadIdx.x;      // [96][192] row-major in
    if (idx < CDIM * 2 * CDIM) {
        int n = idx / (2 * CDIM), k = idx % (2 * CDIM);
        Wt[(size_t)k * CDIM + n] = W[idx];
    }
}

// ---------------------------------------------------------------------------
// Stage-1 tensor GEMM (HMMA): Y = X @ W^T + b, bf16 2-term compensated.
// Grid (2048, 3, 2); block 256 (8 warps, 4x2 warp grid, 32x64 warp tiles).
// K = 96 loaded one-shot into smem (pitch 104 bf16 -> conflict-free ldmatrix).
// Y written row-major fp32 [token][384].
// ---------------------------------------------------------------------------
#define PB 104                                // smem pitch (bf16 elems)
#define MATB (128 * PB * 2)                   // 26624 B per matrix tile
#define MMA_SMEM (4 * MATB)                   // 106496 B

__global__ __launch_bounds__(256)
void mma_gemm(const __nv_bfloat16* __restrict__ XsH,
              const __nv_bfloat16* __restrict__ XsL,
              const __nv_bfloat16* __restrict__ XeH,
              const __nv_bfloat16* __restrict__ XeL,
              const __nv_bfloat16* __restrict__ WsH,
              const __nv_bfloat16* __restrict__ WsL,
              const __nv_bfloat16* __restrict__ WeH,
              const __nv_bfloat16* __restrict__ WeL,
              const float* __restrict__ bs, const float* __restrict__ be,
              float* __restrict__ Ys, float* __restrict__ Ye)
{
    extern __shared__ char smc[];
    const unsigned sb = (unsigned)__cvta_generic_to_shared(smc);

    const int t    = threadIdx.x;
    const int lane = t & 31;
    const int wid  = t >> 5;
    const int mBase = blockIdx.x * 128;
    const int nBase = blockIdx.y * 128;
    const int z     = blockIdx.z;

    const __nv_bfloat16* Ah = z ? XeH : XsH;
    const __nv_bfloat16* Al = z ? XeL : XsL;
    const __nv_bfloat16* Bh = z ? WeH : WsH;
    const __nv_bfloat16* Bl = z ? WeL : WsL;
    const float* bias = z ? be : bs;
    float* Y = z ? g_Ye : g_Ys;

    // ---- one-shot fill: 4 matrices x 128 rows x 12 granules (16B) ----
    {
        const __nv_bfloat16* srcs[4] = {
            Ah + (size_t)mBase * CDIM, Al + (size_t)mBase * CDIM,
            Bh + (size_t)nBase * CDIM, Bl + (size_t)nBase * CDIM };
        #pragma unroll
        for (int m = 0; m < 4; m++) {
            const __nv_bfloat16* src = srcs[m];
            unsigned dst = sb + m * MATB;
            #pragma unroll
            for (int it = 0; it < 6; it++) {
                int g   = t + 256 * it;        // 0..1535
                int row = g / 12;
                int gr  = g % 12;
                cpa16(dst + row * (PB * 2) + gr * 16, src + row * CDIM + gr * 8);
            }
        }
        cpa_commit();
        asm volatile("cp.async.wait_group 0;");
    }
    __syncthreads();

    const int mW = (wid & 3) * 32;
    const int nW = (wid >> 2) * 64;

    float D[16][4];
    #pragma unroll
    for (int i = 0; i < 16; i++)
        #pragma unroll
        for (int j = 0; j < 4; j++) D[i][j] = 0.f;

    const unsigned frow = (unsigned)(lane & 15);
    const unsigned fkof = (unsigned)(lane >> 4) * 8;

    #pragma unroll
    for (int s = 0; s < 6; s++) {
        const unsigned k0 = s * 16;
        unsigned ah[2][4], al[2][4];
        #pragma unroll
        for (int m = 0; m < 2; m++) {
            unsigned off = ((mW + m * 16 + frow) * PB + k0 + fkof) * 2;
            ldsm4(ah[m], sb + off);
            ldsm4(al[m], sb + MATB + off);
        }
        #pragma unroll
        for (int p = 0; p < 4; p++) {
            unsigned boff = ((nW + p * 16 + frow) * PB + k0 + fkof) * 2;
            unsigned bh[4], bl[4];
            ldsm4(bh, sb + 2 * MATB + boff);
            ldsm4(bl, sb + 3 * MATB + boff);
            #pragma unroll
            for (int m = 0; m < 2; m++) {
                #pragma unroll
                for (int na = 0; na < 2; na++) {
                    float* d = D[m * 8 + p * 2 + na];
                    mma16816(d, ah[m], bh[na], bh[na + 2]);
                    mma16816(d, ah[m], bl[na], bl[na + 2]);
                    mma16816(d, al[m], bh[na], bh[na + 2]);
                }
            }
        }
    }

    // ---- epilogue: bias + float2 stores, row-major Y ----
    #pragma unroll
    for (int m = 0; m < 2; m++) {
        int rA = mBase + mW + m * 16 + (lane >> 2);
        #pragma unroll
        for (int n = 0; n < 8; n++) {
            int col = nBase + nW + n * 8 + (lane & 3) * 2;
            float2 bv = *(const float2*)&bias[col];
            float* d = D[m * 8 + n];
            float2 r0; r0.x = d[0] + bv.x; r0.y = d[1] + bv.y;
            float2 r1; r1.x = d[2] + bv.x; r1.y = d[3] + bv.y;
            *(float2*)&Y[(size_t)rA * K4 + col]       = r0;
            *(float2*)&Y[(size_t)(rA + 8) * K4 + col] = r1;
        }
    }
}

// ---------------------------------------------------------------------------
// Window attention (R11-best, unchanged). Grid (BATCH, NHEADS, 2), 128 thr.
// ---------------------------------------------------------------------------
#define TP 36
#define TSZ (NTOK * TP)

__global__ __launch_bounds__(128, 4)
void attn_kernel()
{
    __shared__ float tiles[4 * TSZ];           // k, v, qA, qB

    const int b = blockIdx.x;
    const int h = blockIdx.y;
    const int z = blockIdx.z;

    const float* __restrict__ Y = z ? g_Ye : g_Ys;
    const float  sclA = z ? 1.0f  : SCALE;
    const float  sclB = z ? SCALE : SCALE * SCALE;
    float* outA = g_MvT + (size_t)((z ? CDIM : 0) + h * HD) * MTOK;
    float* outB = g_MhT + (size_t)((z ? 0 : CDIM) + h * HD) * MTOK;
    const float* bTA = g_biasT + (size_t)((z ? 1 : 0) * NHEADS + h) * (NTOK * NTOK);
    const float* bTB = g_biasT + (size_t)((z ? 2 : 3) * NHEADS + h) * (NTOK * NTOK);

    const int t    = threadIdx.x;
    const int lane = t & 31;
    const int warp = t >> 5;

    #pragma unroll
    for (int j4 = 0; j4 < 4; j4++) {
        #pragma unroll
        for (int r = 0; r < 16; r++) {
            int i = warp * 16 + r;
            tiles[j4 * TSZ + i * TP + lane] =
                Y[(size_t)(b * NTOK + i) * K4 + j4 * CDIM + h * HD + lane];
        }
    }
    __syncthreads();

    const int   type = warp >> 1;
    const int   half = warp & 1;
    const int   row  = half * 32 + lane;
    const float scl  = type ? sclB : sclA;
    const float* Kt  = tiles;
    const float* Vt  = tiles + TSZ;
    const float* qp  = tiles + (2 + type) * TSZ + row * TP;
    const float* bT  = (type ? bTB : bTA) + row;
    float* outP      = type ? outB : outA;

    u64 qr2[16];
    #pragma unroll
    for (int c = 0; c < 8; c++) {
        ulonglong2 v2 = *(const ulonglong2*)(qp + 4 * c);
        qr2[2 * c + 0] = v2.x;
        qr2[2 * c + 1] = v2.y;
    }

    float sc[NTOK];
    #pragma unroll
    for (int j = 0; j < NTOK; j++) {
        const float* kj = Kt + j * TP;
        float bj = bT[j * NTOK];
        u64 sA = 0ull, sB = 0ull, sC = 0ull, sD = 0ull;
        #pragma unroll
        for (int c = 0; c < 4; c++) {
            ulonglong2 k0 = *(const ulonglong2*)(kj + 8 * c);
            ulonglong2 k1 = *(const ulonglong2*)(kj + 8 * c + 4);
            fma2(sA, qr2[4 * c + 0], k0.x);
            fma2(sB, qr2[4 * c + 1], k0.y);
            fma2(sC, qr2[4 * c + 2], k1.x);
            fma2(sD, qr2[4 * c + 3], k1.y);
        }
        u64 sT = add2(add2(sA, sB), add2(sC, sD));
        float lo, hi;
        unpack2(lo, hi, sT);
        sc[j] = fmaf(scl, lo + hi, bj);
    }

    float mx = -1e30f;
    #pragma unroll
    for (int j = 0; j < NTOK; j++) mx = fmaxf(mx, sc[j]);
    float sum = 0.f;
    #pragma unroll
    for (int j = 0; j < NTOK; j++) {
        float e = fast_exp(sc[j] - mx);
        sc[j] = e;
        sum += e;
    }
    const float inv = 1.f / sum;

    u64 ou2[16];
    #pragma unroll
    for (int c = 0; c < 16; c++) ou2[c] = 0ull;
    #pragma unroll
    for (int j = 0; j < NTOK; j++) {
        const u64 p2 = pack2(sc[j], sc[j]);
        const float* vj = Vt + j * TP;
        #pragma unroll
        for (int c = 0; c < 8; c++) {
            ulonglong2 vv = *(const ulonglong2*)(vj + 4 * c);
            fma2(ou2[2 * c + 0], p2, vv.x);
            fma2(ou2[2 * c + 1], p2, vv.y);
        }
    }

    float* op = outP + (size_t)b * NTOK + row;
    #pragma unroll
    for (int c = 0; c < 16; c++) {
        float x0, x1;
        unpack2(x0, x1, ou2[c]);
        op[(size_t)(2 * c + 0) * MTOK] = x0 * inv;
        op[(size_t)(2 * c + 1) * MTOK] = x1 * inv;
    }
}

// ---------------------------------------------------------------------------
// Stage-3 GEMM (FFMA2, k-major A): C[M,96] = At[K,M]^T @ Wt[K,96] + bias
// ---------------------------------------------------------------------------
#define BM 128
#define BKC 16
#define APAD 132

__global__ __launch_bounds__(256, 2)
void gemm_t3(const float* __restrict__ At, const float* __restrict__ Wt,
             const float* __restrict__ bias, float* __restrict__ Cout,
             int K, int Nn)
{
    __shared__ float As[2][BKC][APAD];
    __shared__ float Bs[2][BKC][APAD];

    const int t     = threadIdx.x;
    const int mBase = blockIdx.x * BM;
    const int kk    = t & 15;
    const int rr    = t >> 4;
    const int tx    = t & 15;
    const int ty    = t >> 4;

    const unsigned sA = (unsigned)__cvta_generic_to_shared(&As[0][0][0]);
    const unsigned sB = (unsigned)__cvta_generic_to_shared(&Bs[0][0][0]);

    u64 acc[8][3];
    #pragma unroll
    for (int i = 0; i < 8; i++)
        #pragma unroll
        for (int j = 0; j < 3; j++) acc[i][j] = 0ull;

    auto issue = [&](int k0, int buf) {
        const float* aRow = At + (size_t)(k0 + kk) * MTOK + mBase;
        const float* bRow = Wt + (size_t)(k0 + kk) * Nn;
        unsigned dA = sA + (unsigned)(((buf * BKC + kk) * APAD) * 4);
        unsigned dB = sB + (unsigned)(((buf * BKC + kk) * APAD) * 4);
        #pragma unroll
        for (int r = 0; r < 2; r++) {
            int g = rr * 4 + 64 * r;
            cpa16(dA + g * 4, aRow + g);
            cpa16z(dB + g * 4, bRow + g, g < Nn);
        }
        cpa_commit();
    };

    const int NC = K / BKC;
    issue(0, 0);

    for (int c = 0; c < NC; c++) {
        const int buf = c & 1;
        if (c + 1 < NC) {
            issue((c + 1) * BKC, (c + 1) & 1);
            asm volatile("cp.async.wait_group 1;");
        } else {
            asm volatile("cp.async.wait_group 0;");
        }
        __syncthreads();

        const float (*Ab)[APAD] = As[buf];
        const float (*Bb)[APAD] = Bs[buf];
        #pragma unroll
        for (int q = 0; q < BKC; q++) {
            float4 a0 = *(const float4*)&Ab[q][tx * 4];
            float4 a1 = *(const float4*)&Ab[q][64 + tx * 4];
            u64 bn2[3];
            ulonglong2 bb0 = *(const ulonglong2*)&Bb[q][ty * 4];
            bn2[0] = bb0.x; bn2[1] = bb0.y;
            bn2[2] = *(const u64*)&Bb[q][64 + ty * 2];
            float am[8] = {a0.x, a0.y, a0.z, a0.w, a1.x, a1.y, a1.z, a1.w};
            #pragma unroll
            for (int i = 0; i < 8; i++) {
                u64 am2 = pack2(am[i], am[i]);
                #pragma unroll
                for (int j = 0; j < 3; j++)
                    fma2(acc[i][j], am2, bn2[j]);
            }
        }
        __syncthreads();
    }

    #pragma unroll
    for (int ih = 0; ih < 2; ih++) {
        #pragma unroll
        for (int i = 0; i < 4; i++) {
            int row = mBase + ih * 64 + tx * 4 + i;
            {
                int col = ty * 4;
                float4 bv = *(const float4*)&bias[col];
                float x0, x1, x2, x3;
                unpack2(x0, x1, acc[ih * 4 + i][0]);
                unpack2(x2, x3, acc[ih * 4 + i][1]);
                float4 r;
                r.x = x0 + bv.x; r.y = x1 + bv.y;
                r.z = x2 + bv.z; r.w = x3 + bv.w;
                *(float4*)&Cout[(size_t)row * Nn + col] = r;
            }
            {
                int col = 64 + ty * 2;
                float2 bv = *(const float2*)&bias[col];
                float x0, x1;
                unpack2(x0, x1, acc[ih * 4 + i][2]);
                float2 r;
                r.x = x0 + bv.x; r.y = x1 + bv.y;
                *(float2*)&Cout[(size_t)row * Nn + col] = r;
            }
        }
    }
}

// ---------------------------------------------------------------------------
// Launch
// ---------------------------------------------------------------------------
extern "C" void kernel_launch(void* const* d_in, const int* in_sizes, int n_in,
                              void* d_out, int out_size)
{
    const float* input_x = (const float*)d_in[0];
    const float* state_x = (const float*)d_in[1];
    const float* Ws      = (const float*)d_in[2];
    const float* bs      = (const float*)d_in[3];
    const float* We      = (const float*)d_in[4];
    const float* be      = (const float*)d_in[5];
    const float* tcv     = (const float*)d_in[6];
    const float* tsv     = (const float*)d_in[7];
    const float* tch     = (const float*)d_in[8];
    const float* tsh     = (const float*)d_in[9];
    const float* Wpv     = (const float*)d_in[10];
    const float* bpv     = (const float*)d_in[11];
    const float* Wph     = (const float*)d_in[12];
    const float* bph     = (const float*)d_in[13];
    const int*   rel_idx = (const int*)d_in[14];

    float* out   = (float*)d_out;
    float* state = out + (size_t)MTOK * CDIM;

    __nv_bfloat16 *pXsH, *pXsL, *pXeH, *pXeL, *pWsH, *pWsL, *pWeH, *pWeL;
    float *pYs, *pYe, *pMvT, *pMhT, *pWpvT, *pWphT;
    cudaGetSymbolAddress((void**)&pXsH, g_Xs_hi);
    cudaGetSymbolAddress((void**)&pXsL, g_Xs_lo);
    cudaGetSymbolAddress((void**)&pXeH, g_Xe_hi);
    cudaGetSymbolAddress((void**)&pXeL, g_Xe_lo);
    cudaGetSymbolAddress((void**)&pWsH, g_Ws_hi);
    cudaGetSymbolAddress((void**)&pWsL, g_Ws_lo);
    cudaGetSymbolAddress((void**)&pWeH, g_We_hi);
    cudaGetSymbolAddress((void**)&pWeL, g_We_lo);
    cudaGetSymbolAddress((void**)&pYs,  g_Ys);
    cudaGetSymbolAddress((void**)&pYe,  g_Ye);
    cudaGetSymbolAddress((void**)&pMvT, g_MvT);
    cudaGetSymbolAddress((void**)&pMhT, g_MhT);
    cudaGetSymbolAddress((void**)&pWpvT, g_WpvT);
    cudaGetSymbolAddress((void**)&pWphT, g_WphT);

    cudaFuncSetAttribute(mma_gemm,
                         cudaFuncAttributeMaxDynamicSharedMemorySize, MMA_SMEM);

    // Prepass: converts (1-4), bias gather (5)
    {
        size_t nX = (size_t)MTOK * CDIM;
        convert_split<<<(unsigned)((nX / 4 + 255) / 256), 256>>>(state_x, pXsH, pXsL, nX);
        convert_split<<<(unsigned)((nX / 4 + 255) / 256), 256>>>(input_x, pXeH, pXeL, nX);
        size_t nW = (size_t)K4 * CDIM;
        convert_split<<<(unsigned)((nW / 4 + 255) / 256), 256>>>(Ws, pWsH, pWsL, nW);
        convert_split<<<(unsigned)((nW / 4 + 255) / 256), 256>>>(We, pWeH, pWeL, nW);
        dim3 gb(NTOK * NTOK / 256, 4, NHEADS);
        bias_gather<<<gb, 256>>>(tcv, tsv, tch, tsh, rel_idx);
    }

    // Stage 1 (launch #6 — profiled by ncu -s 5): both projections, tensor HMMA
    {
        dim3 grid(MTOK / 128, K4 / 128, 2);    // (2048, 3, 2)
        mma_gemm<<<grid, 256, MMA_SMEM>>>(pXsH, pXsL, pXeH, pXeL,
                                          pWsH, pWsL, pWeH, pWeL,
                                          bs, be, pYs, pYe);
    }

    // Stage-3 weight transposes (needed only before gemm_t3)
    {
        dim3 gw((CDIM * 2 * CDIM + 255) / 256, 2);
        transpose_w2<<<gw, 256>>>(Wpv, Wph);
    }

    // Stage 2: window attention
    {
        dim3 grid(BATCH, NHEADS, 2);
        attn_kernel<<<grid, 128>>>();
    }

    // Stage 3: output projections
    {
        dim3 grid(MTOK / BM, 1);
        gemm_t3<<<grid, 256>>>(pMvT, pWpvT, bpv, out,   2 * CDIM, CDIM);
        gemm_t3<<<grid, 256>>>(pMhT, pWphT, bph, state, 2 * CDIM, CDIM);
    }
}

// round 14
// speedup vs baseline: 2.0342x; 1.1048x over previous
#include <cuda_runtime.h>
#include <cuda_bf16.h>
#include <math.h>

// ---------------------------------------------------------------------------
// Problem constants
// ---------------------------------------------------------------------------
#define BATCH   4096
#define NTOK    64
#define CDIM    96
#define NHEADS  3
#define HD      32
#define K4      384
#define MTOK    (BATCH * NTOK)               // 262144 tokens
#define SCALE   0.17677669529663687f

// ---------------------------------------------------------------------------
// Scratch (device globals)
// ---------------------------------------------------------------------------
__device__ __nv_bfloat16 g_Xs_hi[(size_t)MTOK * CDIM];
__device__ __nv_bfloat16 g_Xs_lo[(size_t)MTOK * CDIM];
__device__ __nv_bfloat16 g_Xe_hi[(size_t)MTOK * CDIM];
__device__ __nv_bfloat16 g_Xe_lo[(size_t)MTOK * CDIM];
__device__ __nv_bfloat16 g_Ws_hi[K4 * CDIM];
__device__ __nv_bfloat16 g_Ws_lo[K4 * CDIM];
__device__ __nv_bfloat16 g_We_hi[K4 * CDIM];
__device__ __nv_bfloat16 g_We_lo[K4 * CDIM];
__device__ __nv_bfloat16 g_Wpv_hi[CDIM * 2 * CDIM];   // [96][192] row-major
__device__ __nv_bfloat16 g_Wpv_lo[CDIM * 2 * CDIM];
__device__ __nv_bfloat16 g_Wph_hi[CDIM * 2 * CDIM];
__device__ __nv_bfloat16 g_Wph_lo[CDIM * 2 * CDIM];
__device__ float g_Ys [(size_t)MTOK * K4];            // row-major [token][384]
__device__ float g_Ye [(size_t)MTOK * K4];
// Attention merges, ROW-MAJOR bf16 hi/lo: Mv = [cv | sv], Mh = [ch | sh]
__device__ __nv_bfloat16 g_Mv_hi[(size_t)MTOK * 2 * CDIM];
__device__ __nv_bfloat16 g_Mv_lo[(size_t)MTOK * 2 * CDIM];
__device__ __nv_bfloat16 g_Mh_hi[(size_t)MTOK * 2 * CDIM];
__device__ __nv_bfloat16 g_Mh_lo[(size_t)MTOK * 2 * CDIM];
__device__ float g_biasT[4 * NHEADS * NTOK * NTOK];   // [tbl][h][j*64+i]

// ---------------------------------------------------------------------------
// Packed f32x2 helpers
// ---------------------------------------------------------------------------
typedef unsigned long long u64;

__device__ __forceinline__ u64 pack2(float lo, float hi)
{
    u64 r;
    asm("mov.b64 %0, {%1, %2};" : "=l"(r)
        : "r"(__float_as_uint(lo)), "r"(__float_as_uint(hi)));
    return r;
}
__device__ __forceinline__ void unpack2(float& lo, float& hi, u64 v)
{
    unsigned a, b;
    asm("mov.b64 {%0, %1}, %2;" : "=r"(a), "=r"(b) : "l"(v));
    lo = __uint_as_float(a);
    hi = __uint_as_float(b);
}
__device__ __forceinline__ void fma2(u64& d, u64 a, u64 b)
{
    asm("fma.rn.f32x2 %0, %1, %2, %0;" : "+l"(d) : "l"(a), "l"(b));
}
__device__ __forceinline__ u64 add2(u64 a, u64 b)
{
    u64 r;
    asm("add.rn.f32x2 %0, %1, %2;" : "=l"(r) : "l"(a), "l"(b));
    return r;
}

__device__ __forceinline__ float fast_exp(float x)
{
    const float L2E   = 1.4426950408889634f;
    const float MAGIC = 12582912.0f;
    float y = x * L2E;
    float t = y + MAGIC;
    float f = y - (t - MAGIC);
    int   i = __float_as_int(t) - 0x4B400000;
    float p = 1.33335581e-3f;
    p = fmaf(p, f, 9.61804886e-3f);
    p = fmaf(p, f, 5.55041087e-2f);
    p = fmaf(p, f, 2.40226507e-1f);
    p = fmaf(p, f, 6.93147182e-1f);
    p = fmaf(p, f, 1.0f);
    return __int_as_float(__float_as_int(p) + (i << 23));
}

// ---------------------------------------------------------------------------
// cp.async helpers
// ---------------------------------------------------------------------------
__device__ __forceinline__ void cpa16(unsigned dst, const void* src)
{
    asm volatile("cp.async.ca.shared.global [%0], [%1], 16;"
                 :: "r"(dst), "l"(src));
}
__device__ __forceinline__ void cpa_commit()
{
    asm volatile("cp.async.commit_group;");
}

// ---------------------------------------------------------------------------
// mma.sync / ldmatrix (baseline sm_80 PTX — compiles under sm_103 target)
// ---------------------------------------------------------------------------
__device__ __forceinline__ void ldsm4(unsigned* r, unsigned addr)
{
    asm volatile("ldmatrix.sync.aligned.m8n8.x4.shared.b16 {%0,%1,%2,%3}, [%4];"
                 : "=r"(r[0]), "=r"(r[1]), "=r"(r[2]), "=r"(r[3]) : "r"(addr));
}
__device__ __forceinline__ void mma16816(float* d, const unsigned* a,
                                         unsigned b0, unsigned b1)
{
    asm volatile(
        "mma.sync.aligned.m16n8k16.row.col.f32.bf16.bf16.f32 "
        "{%0,%1,%2,%3}, {%4,%5,%6,%7}, {%8,%9}, {%0,%1,%2,%3};"
        : "+f"(d[0]), "+f"(d[1]), "+f"(d[2]), "+f"(d[3])
        : "r"(a[0]), "r"(a[1]), "r"(a[2]), "r"(a[3]), "r"(b0), "r"(b1));
}

// ---------------------------------------------------------------------------
// Prepass kernels
// ---------------------------------------------------------------------------
__global__ void bias_gather(const float* __restrict__ tcv,
                            const float* __restrict__ tsv,
                            const float* __restrict__ tch,
                            const float* __restrict__ tsh,
                            const int*   __restrict__ rel_idx)
{
    const int tbl = blockIdx.y;
    const int h   = blockIdx.z;
    const float* T = (tbl == 0) ? tcv : (tbl == 1) ? tsv : (tbl == 2) ? tch : tsh;
    int idx = blockIdx.x * 256 + threadIdx.x;      // idx = i*64 + j
    int i = idx >> 6, j = idx & 63;
    g_biasT[(size_t)(tbl * NHEADS + h) * (NTOK * NTOK) + j * NTOK + i] =
        T[rel_idx[idx] * NHEADS + h];
}

__global__ __launch_bounds__(256)
void convert_split(const float* __restrict__ X,
                   __nv_bfloat16* __restrict__ hi,
                   __nv_bfloat16* __restrict__ lo, size_t n)
{
    size_t idx = ((size_t)blockIdx.x * 256 + threadIdx.x) * 4;
    if (idx >= n) return;
    float4 v = *(const float4*)(X + idx);
    float xs[4] = {v.x, v.y, v.z, v.w};
    __nv_bfloat16 h4[4], l4[4];
    #pragma unroll
    for (int c = 0; c < 4; c++) {
        __nv_bfloat16 hb = __float2bfloat16(xs[c]);
        h4[c] = hb;
        l4[c] = __float2bfloat16(xs[c] - __bfloat162float(hb));
    }
    *(ulonglong1*)(hi + idx) = *(ulonglong1*)h4;
    *(ulonglong1*)(lo + idx) = *(ulonglong1*)l4;
}

// ---------------------------------------------------------------------------
// Stage-1 tensor GEMM (HMMA): Y = X @ W^T + b, bf16 2-term compensated.
// Grid (2048, 3, 2); block 256 (8 warps, 4x2 warp grid, 32x64 warp tiles).
// K = 96 loaded one-shot into smem (pitch 104 bf16 -> conflict-free ldmatrix).
// Y written row-major fp32 [token][384].
// ---------------------------------------------------------------------------
#define PB 104                                // smem pitch (bf16 elems)
#define MATB (128 * PB * 2)                   // 26624 B per matrix tile
#define MMA_SMEM (4 * MATB)                   // 106496 B

__global__ __launch_bounds__(256)
void mma_gemm(const __nv_bfloat16* __restrict__ XsH,
              const __nv_bfloat16* __restrict__ XsL,
              const __nv_bfloat16* __restrict__ XeH,
              const __nv_bfloat16* __restrict__ XeL,
              const __nv_bfloat16* __restrict__ WsH,
              const __nv_bfloat16* __restrict__ WsL,
              const __nv_bfloat16* __restrict__ WeH,
              const __nv_bfloat16* __restrict__ WeL,
              const float* __restrict__ bs, const float* __restrict__ be,
              float* __restrict__ Ys, float* __restrict__ Ye)
{
    extern __shared__ char smc[];
    const unsigned sb = (unsigned)__cvta_generic_to_shared(smc);

    const int t    = threadIdx.x;
    const int lane = t & 31;
    const int wid  = t >> 5;
    const int mBase = blockIdx.x * 128;
    const int nBase = blockIdx.y * 128;
    const int z     = blockIdx.z;

    const __nv_bfloat16* Ah = z ? XeH : XsH;
    const __nv_bfloat16* Al = z ? XeL : XsL;
    const __nv_bfloat16* Bh = z ? WeH : WsH;
    const __nv_bfloat16* Bl = z ? WeL : WsL;
    const float* bias = z ? be : bs;
    float* Y = z ? g_Ye : g_Ys;

    {
        const __nv_bfloat16* srcs[4] = {
            Ah + (size_t)mBase * CDIM, Al + (size_t)mBase * CDIM,
            Bh + (size_t)nBase * CDIM, Bl + (size_t)nBase * CDIM };
        #pragma unroll
        for (int m = 0; m < 4; m++) {
            const __nv_bfloat16* src = srcs[m];
            unsigned dst = sb + m * MATB;
            #pragma unroll
            for (int it = 0; it < 6; it++) {
                int g   = t + 256 * it;        // 0..1535
                int row = g / 12;
                int gr  = g % 12;
                cpa16(dst + row * (PB * 2) + gr * 16, src + row * CDIM + gr * 8);
            }
        }
        cpa_commit();
        asm volatile("cp.async.wait_group 0;");
    }
    __syncthreads();

    const int mW = (wid & 3) * 32;
    const int nW = (wid >> 2) * 64;

    float D[16][4];
    #pragma unroll
    for (int i = 0; i < 16; i++)
        #pragma unroll
        for (int j = 0; j < 4; j++) D[i][j] = 0.f;

    const unsigned frow = (unsigned)(lane & 15);
    const unsigned fkof = (unsigned)(lane >> 4) * 8;

    #pragma unroll
    for (int s = 0; s < 6; s++) {
        const unsigned k0 = s * 16;
        unsigned ah[2][4], al[2][4];
        #pragma unroll
        for (int m = 0; m < 2; m++) {
            unsigned off = ((mW + m * 16 + frow) * PB + k0 + fkof) * 2;
            ldsm4(ah[m], sb + off);
            ldsm4(al[m], sb + MATB + off);
        }
        #pragma unroll
        for (int p = 0; p < 4; p++) {
            unsigned boff = ((nW + p * 16 + frow) * PB + k0 + fkof) * 2;
            unsigned bh[4], bl[4];
            ldsm4(bh, sb + 2 * MATB + boff);
            ldsm4(bl, sb + 3 * MATB + boff);
            #pragma unroll
            for (int m = 0; m < 2; m++) {
                #pragma unroll
                for (int na = 0; na < 2; na++) {
                    float* d = D[m * 8 + p * 2 + na];
                    mma16816(d, ah[m], bh[na], bh[na + 2]);
                    mma16816(d, ah[m], bl[na], bl[na + 2]);
                    mma16816(d, al[m], bh[na], bh[na + 2]);
                }
            }
        }
    }

    #pragma unroll
    for (int m = 0; m < 2; m++) {
        int rA = mBase + mW + m * 16 + (lane >> 2);
        #pragma unroll
        for (int n = 0; n < 8; n++) {
            int col = nBase + nW + n * 8 + (lane & 3) * 2;
            float2 bv = *(const float2*)&bias[col];
            float* d = D[m * 8 + n];
            float2 r0; r0.x = d[0] + bv.x; r0.y = d[1] + bv.y;
            float2 r1; r1.x = d[2] + bv.x; r1.y = d[3] + bv.y;
            *(float2*)&Y[(size_t)rA * K4 + col]       = r0;
            *(float2*)&Y[(size_t)(rA + 8) * K4 + col] = r1;
        }
    }
}

// ---------------------------------------------------------------------------
// Window attention. Grid (BATCH, NHEADS, 2), 128 thr. R11-best math; epilogue
// now writes bf16 hi/lo ROW-MAJOR into g_Mv_* / g_Mh_* (stage-3 HMMA layout).
// ---------------------------------------------------------------------------
#define TP 36
#define TSZ (NTOK * TP)

__global__ __launch_bounds__(128, 4)
void attn_kernel()
{
    __shared__ float tiles[4 * TSZ];           // k, v, qA, qB

    const int b = blockIdx.x;
    const int h = blockIdx.y;
    const int z = blockIdx.z;

    const float* __restrict__ Y = z ? g_Ye : g_Ys;
    const float  sclA = z ? 1.0f  : SCALE;
    const float  sclB = z ? SCALE : SCALE * SCALE;
    const float* bTA = g_biasT + (size_t)((z ? 1 : 0) * NHEADS + h) * (NTOK * NTOK);
    const float* bTB = g_biasT + (size_t)((z ? 2 : 3) * NHEADS + h) * (NTOK * NTOK);

    const int t    = threadIdx.x;
    const int lane = t & 31;
    const int warp = t >> 5;

    #pragma unroll
    for (int j4 = 0; j4 < 4; j4++) {
        #pragma unroll
        for (int r = 0; r < 16; r++) {
            int i = warp * 16 + r;
            tiles[j4 * TSZ + i * TP + lane] =
                Y[(size_t)(b * NTOK + i) * K4 + j4 * CDIM + h * HD + lane];
        }
    }
    __syncthreads();

    const int   type = warp >> 1;
    const int   half = warp & 1;
    const int   row  = half * 32 + lane;
    const float scl  = type ? sclB : sclA;
    const float* Kt  = tiles;
    const float* Vt  = tiles + TSZ;
    const float* qp  = tiles + (2 + type) * TSZ + row * TP;
    const float* bT  = (type ? bTB : bTA) + row;

    // output placement (row-major M[token][192]):
    //   typeA: Mv, col = z*96 + h*32  (z0=cv first half, z1=sv second half)
    //   typeB: Mh, col = (1-z)*96 + h*32 (z0=sh second half, z1=ch first half)
    __nv_bfloat16* oHi = type ? g_Mh_hi : g_Mv_hi;
    __nv_bfloat16* oLo = type ? g_Mh_lo : g_Mv_lo;
    const int colb = (type ? (z ? 0 : CDIM) : (z ? CDIM : 0)) + h * HD;

    u64 qr2[16];
    #pragma unroll
    for (int c = 0; c < 8; c++) {
        ulonglong2 v2 = *(const ulonglong2*)(qp + 4 * c);
        qr2[2 * c + 0] = v2.x;
        qr2[2 * c + 1] = v2.y;
    }

    float sc[NTOK];
    #pragma unroll
    for (int j = 0; j < NTOK; j++) {
        const float* kj = Kt + j * TP;
        float bj = bT[j * NTOK];
        u64 sA = 0ull, sB = 0ull, sC = 0ull, sD = 0ull;
        #pragma unroll
        for (int c = 0; c < 4; c++) {
            ulonglong2 k0 = *(const ulonglong2*)(kj + 8 * c);
            ulonglong2 k1 = *(const ulonglong2*)(kj + 8 * c + 4);
            fma2(sA, qr2[4 * c + 0], k0.x);
            fma2(sB, qr2[4 * c + 1], k0.y);
            fma2(sC, qr2[4 * c + 2], k1.x);
            fma2(sD, qr2[4 * c + 3], k1.y);
        }
        u64 sT = add2(add2(sA, sB), add2(sC, sD));
        float lo, hi;
        unpack2(lo, hi, sT);
        sc[j] = fmaf(scl, lo + hi, bj);
    }

    float mx = -1e30f;
    #pragma unroll
    for (int j = 0; j < NTOK; j++) mx = fmaxf(mx, sc[j]);
    float sum = 0.f;
    #pragma unroll
    for (int j = 0; j < NTOK; j++) {
        float e = fast_exp(sc[j] - mx);
        sc[j] = e;
        sum += e;
    }
    const float inv = 1.f / sum;

    u64 ou2[16];
    #pragma unroll
    for (int c = 0; c < 16; c++) ou2[c] = 0ull;
    #pragma unroll
    for (int j = 0; j < NTOK; j++) {
        const u64 p2 = pack2(sc[j], sc[j]);
        const float* vj = Vt + j * TP;
        #pragma unroll
        for (int c = 0; c < 8; c++) {
            ulonglong2 vv = *(const ulonglong2*)(vj + 4 * c);
            fma2(ou2[2 * c + 0], p2, vv.x);
            fma2(ou2[2 * c + 1], p2, vv.y);
        }
    }

    // ---- bf16 hi/lo split + row-major stores (16B-aligned uint4) ----
    unsigned hpk[16], lpk[16];
    #pragma unroll
    for (int c = 0; c < 16; c++) {
        float x0, x1;
        unpack2(x0, x1, ou2[c]);
        x0 *= inv; x1 *= inv;
        __nv_bfloat16 h0 = __float2bfloat16(x0);
        __nv_bfloat16 h1 = __float2bfloat16(x1);
        __nv_bfloat16 l0 = __float2bfloat16(x0 - __bfloat162float(h0));
        __nv_bfloat16 l1 = __float2bfloat16(x1 - __bfloat162float(h1));
        __nv_bfloat162 hh; hh.x = h0; hh.y = h1;
        __nv_bfloat162 ll; ll.x = l0; ll.y = l1;
        hpk[c] = *(unsigned*)&hh;
        lpk[c] = *(unsigned*)&ll;
    }
    size_t base = (size_t)(b * NTOK + row) * (2 * CDIM) + colb;
    #pragma unroll
    for (int q = 0; q < 4; q++) {
        *(uint4*)(oHi + base + 8 * q) = ((uint4*)hpk)[q];
        *(uint4*)(oLo + base + 8 * q) = ((uint4*)lpk)[q];
    }
}

// ---------------------------------------------------------------------------
// Stage-3 tensor GEMM (HMMA): C[M,96] = M[token,192] @ W[96,192]^T + bias.
// Grid (2048, 1, 2); block 256 (8 warps, 4m x 2n, 32x48 warp tiles).
// K = 192 one-shot in smem, pitch 200 bf16 (conflict-free ldmatrix).
// ---------------------------------------------------------------------------
#define PB2   200
#define AROW2 (PB2 * 2)                       // 400 B
#define S3_AH 0
#define S3_AL (128 * AROW2)                   // 51200
#define S3_BH (2 * 128 * AROW2)               // 102400
#define S3_BL (S3_BH + CDIM * AROW2)          // +38400
#define S3_SMEM (S3_BL + CDIM * AROW2)        // 179200 B

__global__ __launch_bounds__(256)
void mma_gemm3(const float* __restrict__ bpv, const float* __restrict__ bph,
               float* __restrict__ out, float* __restrict__ state)
{
    extern __shared__ char smc[];
    const unsigned sb = (unsigned)__cvta_generic_to_shared(smc);

    const int t    = threadIdx.x;
    const int lane = t & 31;
    const int wid  = t >> 5;
    const int mBase = blockIdx.x * 128;
    const int z     = blockIdx.z;

    const __nv_bfloat16* Ah = z ? g_Mh_hi : g_Mv_hi;
    const __nv_bfloat16* Al = z ? g_Mh_lo : g_Mv_lo;
    const __nv_bfloat16* Bh = z ? g_Wph_hi : g_Wpv_hi;
    const __nv_bfloat16* Bl = z ? g_Wph_lo : g_Wpv_lo;
    const float* bias = z ? bph : bpv;
    float* C = z ? state : out;

    // ---- fill: A 128 rows x 24 granules, B 96 rows x 24 granules ----
    {
        const __nv_bfloat16* aH = Ah + (size_t)mBase * (2 * CDIM);
        const __nv_bfloat16* aL = Al + (size_t)mBase * (2 * CDIM);
        #pragma unroll
        for (int it = 0; it < 12; it++) {
            int g   = t + 256 * it;            // 0..3071
            int row = g / 24;
            int gr  = g % 24;
            cpa16(sb + S3_AH + row * AROW2 + gr * 16, aH + row * (2 * CDIM) + gr * 8);
            cpa16(sb + S3_AL + row * AROW2 + gr * 16, aL + row * (2 * CDIM) + gr * 8);
        }
        #pragma unroll
        for (int it = 0; it < 9; it++) {
            int g = t + 256 * it;              // 0..2303
            int row = g / 24;
            int gr  = g % 24;
            cpa16(sb + S3_BH + row * AROW2 + gr * 16, Bh + row * (2 * CDIM) + gr * 8);
            cpa16(sb + S3_BL + row * AROW2 + gr * 16, Bl + row * (2 * CDIM) + gr * 8);
        }
        cpa_commit();
        asm volatile("cp.async.wait_group 0;");
    }
    __syncthreads();

    const int mW = (wid & 3) * 32;
    const int nW = (wid >> 2) * 48;

    float D[12][4];
    #pragma unroll
    for (int i = 0; i < 12; i++)
        #pragma unroll
        for (int j = 0; j < 4; j++) D[i][j] = 0.f;

    const unsigned frow = (unsigned)(lane & 15);
    const unsigned fkof = (unsigned)(lane >> 4) * 8;

    #pragma unroll
    for (int s = 0; s < 12; s++) {
        const unsigned k0 = s * 16;
        unsigned ah[2][4], al[2][4];
        #pragma unroll
        for (int m = 0; m < 2; m++) {
            unsigned off = ((mW + m * 16 + frow) * PB2 + k0 + fkof) * 2;
            ldsm4(ah[m], sb + S3_AH + off);
            ldsm4(al[m], sb + S3_AL + off);
        }
        #pragma unroll
        for (int p = 0; p < 3; p++) {
            unsigned boff = ((nW + p * 16 + frow) * PB2 + k0 + fkof) * 2;
            unsigned bh[4], bl[4];
            ldsm4(bh, sb + S3_BH + boff);
            ldsm4(bl, sb + S3_BL + boff);
            #pragma unroll
            for (int m = 0; m < 2; m++) {
                #pragma unroll
                for (int na = 0; na < 2; na++) {
                    float* d = D[m * 6 + p * 2 + na];
                    mma16816(d, ah[m], bh[na], bh[na + 2]);
                    mma16816(d, ah[m], bl[na], bl[na + 2]);
                    mma16816(d, al[m], bh[na], bh[na + 2]);
                }
            }
        }
    }

    // ---- epilogue: bias + float2 stores into C[token][96] ----
    #pragma unroll
    for (int m = 0; m < 2; m++) {
        int rA = mBase + mW + m * 16 + (lane >> 2);
        #pragma unroll
        for (int n = 0; n < 6; n++) {
            int col = nW + n * 8 + (lane & 3) * 2;
            float2 bv = *(const float2*)&bias[col];
            float* d = D[m * 6 + n];
            float2 r0; r0.x = d[0] + bv.x; r0.y = d[1] + bv.y;
            float2 r1; r1.x = d[2] + bv.x; r1.y = d[3] + bv.y;
            *(float2*)&C[(size_t)rA * CDIM + col]       = r0;
            *(float2*)&C[(size_t)(rA + 8) * CDIM + col] = r1;
        }
    }
}

// ---------------------------------------------------------------------------
// Launch
// ---------------------------------------------------------------------------
extern "C" void kernel_launch(void* const* d_in, const int* in_sizes, int n_in,
                              void* d_out, int out_size)
{
    const float* input_x = (const float*)d_in[0];
    const float* state_x = (const float*)d_in[1];
    const float* Ws      = (const float*)d_in[2];
    const float* bs      = (const float*)d_in[3];
    const float* We      = (const float*)d_in[4];
    const float* be      = (const float*)d_in[5];
    const float* tcv     = (const float*)d_in[6];
    const float* tsv     = (const float*)d_in[7];
    const float* tch     = (const float*)d_in[8];
    const float* tsh     = (const float*)d_in[9];
    const float* Wpv     = (const float*)d_in[10];
    const float* bpv     = (const float*)d_in[11];
    const float* Wph     = (const float*)d_in[12];
    const float* bph     = (const float*)d_in[13];
    const int*   rel_idx = (const int*)d_in[14];

    float* out   = (float*)d_out;
    float* state = out + (size_t)MTOK * CDIM;

    __nv_bfloat16 *pXsH, *pXsL, *pXeH, *pXeL, *pWsH, *pWsL, *pWeH, *pWeL;
    __nv_bfloat16 *pWpvH, *pWpvL, *pWphH, *pWphL;
    float *pYs, *pYe;
    cudaGetSymbolAddress((void**)&pXsH, g_Xs_hi);
    cudaGetSymbolAddress((void**)&pXsL, g_Xs_lo);
    cudaGetSymbolAddress((void**)&pXeH, g_Xe_hi);
    cudaGetSymbolAddress((void**)&pXeL, g_Xe_lo);
    cudaGetSymbolAddress((void**)&pWsH, g_Ws_hi);
    cudaGetSymbolAddress((void**)&pWsL, g_Ws_lo);
    cudaGetSymbolAddress((void**)&pWeH, g_We_hi);
    cudaGetSymbolAddress((void**)&pWeL, g_We_lo);
    cudaGetSymbolAddress((void**)&pWpvH, g_Wpv_hi);
    cudaGetSymbolAddress((void**)&pWpvL, g_Wpv_lo);
    cudaGetSymbolAddress((void**)&pWphH, g_Wph_hi);
    cudaGetSymbolAddress((void**)&pWphL, g_Wph_lo);
    cudaGetSymbolAddress((void**)&pYs,  g_Ys);
    cudaGetSymbolAddress((void**)&pYe,  g_Ye);

    cudaFuncSetAttribute(mma_gemm,
                         cudaFuncAttributeMaxDynamicSharedMemorySize, MMA_SMEM);
    cudaFuncSetAttribute(mma_gemm3,
                         cudaFuncAttributeMaxDynamicSharedMemorySize, S3_SMEM);

    // Prepass: converts + bias gather
    {
        size_t nX = (size_t)MTOK * CDIM;
        convert_split<<<(unsigned)((nX / 4 + 255) / 256), 256>>>(state_x, pXsH, pXsL, nX);
        convert_split<<<(unsigned)((nX / 4 + 255) / 256), 256>>>(input_x, pXeH, pXeL, nX);
        size_t nW = (size_t)K4 * CDIM;
        convert_split<<<(unsigned)((nW / 4 + 255) / 256), 256>>>(Ws, pWsH, pWsL, nW);
        convert_split<<<(unsigned)((nW / 4 + 255) / 256), 256>>>(We, pWeH, pWeL, nW);
        size_t nP = (size_t)CDIM * 2 * CDIM;
        convert_split<<<(unsigned)((nP / 4 + 255) / 256), 256>>>(Wpv, pWpvH, pWpvL, nP);
        convert_split<<<(unsigned)((nP / 4 + 255) / 256), 256>>>(Wph, pWphH, pWphL, nP);
        dim3 gb(NTOK * NTOK / 256, 4, NHEADS);
        bias_gather<<<gb, 256>>>(tcv, tsv, tch, tsh, rel_idx);
    }

    // Stage 1: projections on HMMA
    {
        dim3 grid(MTOK / 128, K4 / 128, 2);    // (2048, 3, 2)
        mma_gemm<<<grid, 256, MMA_SMEM>>>(pXsH, pXsL, pXeH, pXeL,
                                          pWsH, pWsL, pWeH, pWeL,
                                          bs, be, pYs, pYe);
    }

    // Stage 2: window attention -> bf16 hi/lo row-major merges
    {
        dim3 grid(BATCH, NHEADS, 2);
        attn_kernel<<<grid, 128>>>();
    }

    // Stage 3: output projections on HMMA
    {
        dim3 grid(MTOK / 128, 1, 2);           // (2048, 1, 2)
        mma_gemm3<<<grid, 256, S3_SMEM>>>(bpv, bph, out, state);
    }
}

// round 15
// speedup vs baseline: 2.8012x; 1.3771x over previous
#include <cuda_runtime.h>
#include <cuda_bf16.h>
#include <math.h>

// ---------------------------------------------------------------------------
// Problem constants
// ---------------------------------------------------------------------------
#define BATCH   4096
#define NTOK    64
#define CDIM    96
#define NHEADS  3
#define HD      32
#define K4      384
#define MTOK    (BATCH * NTOK)               // 262144 tokens
#define SCALE   0.17677669529663687f

// ---------------------------------------------------------------------------
// Scratch (device globals)
// ---------------------------------------------------------------------------
__device__ __nv_bfloat16 g_Xs_hi[(size_t)MTOK * CDIM];
__device__ __nv_bfloat16 g_Xs_lo[(size_t)MTOK * CDIM];
__device__ __nv_bfloat16 g_Xe_hi[(size_t)MTOK * CDIM];
__device__ __nv_bfloat16 g_Xe_lo[(size_t)MTOK * CDIM];
__device__ __nv_bfloat16 g_Ws_hi[K4 * CDIM];
__device__ __nv_bfloat16 g_Ws_lo[K4 * CDIM];
__device__ __nv_bfloat16 g_We_hi[K4 * CDIM];
__device__ __nv_bfloat16 g_We_lo[K4 * CDIM];
__device__ __nv_bfloat16 g_Wpv_hi[CDIM * 2 * CDIM];   // [96][192] row-major
__device__ __nv_bfloat16 g_Wpv_lo[CDIM * 2 * CDIM];
__device__ __nv_bfloat16 g_Wph_hi[CDIM * 2 * CDIM];
__device__ __nv_bfloat16 g_Wph_lo[CDIM * 2 * CDIM];
__device__ float g_Ys [(size_t)MTOK * K4];            // row-major [token][384]
__device__ float g_Ye [(size_t)MTOK * K4];
// Attention merges, ROW-MAJOR bf16 hi/lo: Mv = [cv | sv], Mh = [ch | sh]
__device__ __nv_bfloat16 g_Mv_hi[(size_t)MTOK * 2 * CDIM];
__device__ __nv_bfloat16 g_Mv_lo[(size_t)MTOK * 2 * CDIM];
__device__ __nv_bfloat16 g_Mh_hi[(size_t)MTOK * 2 * CDIM];
__device__ __nv_bfloat16 g_Mh_lo[(size_t)MTOK * 2 * CDIM];
__device__ float g_bias[4 * NHEADS * NTOK * NTOK];    // [tbl][h][i*64+j]

typedef unsigned long long u64;

__device__ __forceinline__ float fast_exp(float x)
{
    const float L2E   = 1.4426950408889634f;
    const float MAGIC = 12582912.0f;
    float y = x * L2E;
    float t = y + MAGIC;
    float f = y - (t - MAGIC);
    int   i = __float_as_int(t) - 0x4B400000;
    float p = 1.33335581e-3f;
    p = fmaf(p, f, 9.61804886e-3f);
    p = fmaf(p, f, 5.55041087e-2f);
    p = fmaf(p, f, 2.40226507e-1f);
    p = fmaf(p, f, 6.93147182e-1f);
    p = fmaf(p, f, 1.0f);
    return __int_as_float(__float_as_int(p) + (i << 23));
}

// ---------------------------------------------------------------------------
// cp.async helpers
// ---------------------------------------------------------------------------
__device__ __forceinline__ void cpa16(unsigned dst, const void* src)
{
    asm volatile("cp.async.ca.shared.global [%0], [%1], 16;"
                 :: "r"(dst), "l"(src));
}
__device__ __forceinline__ void cpa_commit()
{
    asm volatile("cp.async.commit_group;");
}

// ---------------------------------------------------------------------------
// mma.sync / ldmatrix (baseline sm_80 PTX — compiles under sm_103 target)
// ---------------------------------------------------------------------------
__device__ __forceinline__ void ldsm4(unsigned* r, unsigned addr)
{
    asm volatile("ldmatrix.sync.aligned.m8n8.x4.shared.b16 {%0,%1,%2,%3}, [%4];"
                 : "=r"(r[0]), "=r"(r[1]), "=r"(r[2]), "=r"(r[3]) : "r"(addr));
}
__device__ __forceinline__ void mma16816(float* d, const unsigned* a,
                                         unsigned b0, unsigned b1)
{
    asm volatile(
        "mma.sync.aligned.m16n8k16.row.col.f32.bf16.bf16.f32 "
        "{%0,%1,%2,%3}, {%4,%5,%6,%7}, {%8,%9}, {%0,%1,%2,%3};"
        : "+f"(d[0]), "+f"(d[1]), "+f"(d[2]), "+f"(d[3])
        : "r"(a[0]), "r"(a[1]), "r"(a[2]), "r"(a[3]), "r"(b0), "r"(b1));
}
// pack {lo=a, hi=b} bf16x2
__device__ __forceinline__ unsigned pkbf(float a, float b)
{
    unsigned r;
    asm("cvt.rn.bf16x2.f32 %0, %1, %2;" : "=r"(r) : "f"(b), "f"(a));
    return r;
}

// ---------------------------------------------------------------------------
// Prepass kernels
// ---------------------------------------------------------------------------
__global__ void bias_gather(const float* __restrict__ tcv,
                            const float* __restrict__ tsv,
                            const float* __restrict__ tch,
                            const float* __restrict__ tsh,
                            const int*   __restrict__ rel_idx)
{
    const int tbl = blockIdx.y;
    const int h   = blockIdx.z;
    const float* T = (tbl == 0) ? tcv : (tbl == 1) ? tsv : (tbl == 2) ? tch : tsh;
    int idx = blockIdx.x * 256 + threadIdx.x;      // idx = i*64 + j
    g_bias[(size_t)(tbl * NHEADS + h) * (NTOK * NTOK) + idx] =
        T[rel_idx[idx] * NHEADS + h];
}

__global__ __launch_bounds__(256)
void convert_split(const float* __restrict__ X,
                   __nv_bfloat16* __restrict__ hi,
                   __nv_bfloat16* __restrict__ lo, size_t n)
{
    size_t idx = ((size_t)blockIdx.x * 256 + threadIdx.x) * 4;
    if (idx >= n) return;
    float4 v = *(const float4*)(X + idx);
    float xs[4] = {v.x, v.y, v.z, v.w};
    __nv_bfloat16 h4[4], l4[4];
    #pragma unroll
    for (int c = 0; c < 4; c++) {
        __nv_bfloat16 hb = __float2bfloat16(xs[c]);
        h4[c] = hb;
        l4[c] = __float2bfloat16(xs[c] - __bfloat162float(hb));
    }
    *(ulonglong1*)(hi + idx) = *(ulonglong1*)h4;
    *(ulonglong1*)(lo + idx) = *(ulonglong1*)l4;
}

// ---------------------------------------------------------------------------
// Stage-1 tensor GEMM (HMMA): Y = X @ W^T + b, bf16 2-term compensated.
// ---------------------------------------------------------------------------
#define PB 104
#define MATB (128 * PB * 2)
#define MMA_SMEM (4 * MATB)

__global__ __launch_bounds__(256)
void mma_gemm(const __nv_bfloat16* __restrict__ XsH,
              const __nv_bfloat16* __restrict__ XsL,
              const __nv_bfloat16* __restrict__ XeH,
              const __nv_bfloat16* __restrict__ XeL,
              const __nv_bfloat16* __restrict__ WsH,
              const __nv_bfloat16* __restrict__ WsL,
              const __nv_bfloat16* __restrict__ WeH,
              const __nv_bfloat16* __restrict__ WeL,
              const float* __restrict__ bs, const float* __restrict__ be,
              float* __restrict__ Ys, float* __restrict__ Ye)
{
    extern __shared__ char smc[];
    const unsigned sb = (unsigned)__cvta_generic_to_shared(smc);

    const int t    = threadIdx.x;
    const int lane = t & 31;
    const int wid  = t >> 5;
    const int mBase = blockIdx.x * 128;
    const int nBase = blockIdx.y * 128;
    const int z     = blockIdx.z;

    const __nv_bfloat16* Ah = z ? XeH : XsH;
    const __nv_bfloat16* Al = z ? XeL : XsL;
    const __nv_bfloat16* Bh = z ? WeH : WsH;
    const __nv_bfloat16* Bl = z ? WeL : WsL;
    const float* bias = z ? be : bs;
    float* Y = z ? g_Ye : g_Ys;

    {
        const __nv_bfloat16* srcs[4] = {
            Ah + (size_t)mBase * CDIM, Al + (size_t)mBase * CDIM,
            Bh + (size_t)nBase * CDIM, Bl + (size_t)nBase * CDIM };
        #pragma unroll
        for (int m = 0; m < 4; m++) {
            const __nv_bfloat16* src = srcs[m];
            unsigned dst = sb + m * MATB;
            #pragma unroll
            for (int it = 0; it < 6; it++) {
                int g   = t + 256 * it;
                int row = g / 12;
                int gr  = g % 12;
                cpa16(dst + row * (PB * 2) + gr * 16, src + row * CDIM + gr * 8);
            }
        }
        cpa_commit();
        asm volatile("cp.async.wait_group 0;");
    }
    __syncthreads();

    const int mW = (wid & 3) * 32;
    const int nW = (wid >> 2) * 64;

    float D[16][4];
    #pragma unroll
    for (int i = 0; i < 16; i++)
        #pragma unroll
        for (int j = 0; j < 4; j++) D[i][j] = 0.f;

    const unsigned frow = (unsigned)(lane & 15);
    const unsigned fkof = (unsigned)(lane >> 4) * 8;

    #pragma unroll
    for (int s = 0; s < 6; s++) {
        const unsigned k0 = s * 16;
        unsigned ah[2][4], al[2][4];
        #pragma unroll
        for (int m = 0; m < 2; m++) {
            unsigned off = ((mW + m * 16 + frow) * PB + k0 + fkof) * 2;
            ldsm4(ah[m], sb + off);
            ldsm4(al[m], sb + MATB + off);
        }
        #pragma unroll
        for (int p = 0; p < 4; p++) {
            unsigned boff = ((nW + p * 16 + frow) * PB + k0 + fkof) * 2;
            unsigned bh[4], bl[4];
            ldsm4(bh, sb + 2 * MATB + boff);
            ldsm4(bl, sb + 3 * MATB + boff);
            #pragma unroll
            for (int m = 0; m < 2; m++) {
                #pragma unroll
                for (int na = 0; na < 2; na++) {
                    float* d = D[m * 8 + p * 2 + na];
                    mma16816(d, ah[m], bh[na], bh[na + 2]);
                    mma16816(d, ah[m], bl[na], bl[na + 2]);
                    mma16816(d, al[m], bh[na], bh[na + 2]);
                }
            }
        }
    }

    #pragma unroll
    for (int m = 0; m < 2; m++) {
        int rA = mBase + mW + m * 16 + (lane >> 2);
        #pragma unroll
        for (int n = 0; n < 8; n++) {
            int col = nBase + nW + n * 8 + (lane & 3) * 2;
            float2 bv = *(const float2*)&bias[col];
            float* d = D[m * 8 + n];
            float2 r0; r0.x = d[0] + bv.x; r0.y = d[1] + bv.y;
            float2 r1; r1.x = d[2] + bv.x; r1.y = d[3] + bv.y;
            *(float2*)&Y[(size_t)rA * K4 + col]       = r0;
            *(float2*)&Y[(size_t)(rA + 8) * K4 + col] = r1;
        }
    }
}

// ---------------------------------------------------------------------------
// Window attention on HMMA. Grid (BATCH, NHEADS, 2); block 256 (8 warps).
// warps 0-3 = type A (16 query rows each), warps 4-7 = type B.
// QK and PV both m16n8k16 bf16 with hi/lo 2-term compensation.
// smem: Q/K pitch 40 halves, V stored transposed [d][j] pitch 72.
// ---------------------------------------------------------------------------
#define PQ  40
#define PV2 72
#define O_KH  0
#define O_KL  2560
#define O_QAH 5120
#define O_QAL 7680
#define O_QBH 10240
#define O_QBL 12800
#define O_VH  15360
#define O_VL  17664
#define ATT_HALVES 19968                      // 39936 B

__global__ __launch_bounds__(256)
void attn_mma()
{
    __shared__ __nv_bfloat16 smh[ATT_HALVES];
    const unsigned sb = (unsigned)__cvta_generic_to_shared(smh);

    const int b = blockIdx.x;
    const int h = blockIdx.y;
    const int z = blockIdx.z;
    const float* __restrict__ Y = z ? g_Ye : g_Ys;

    const int t    = threadIdx.x;
    const int lane = t & 31;
    const int wid  = t >> 5;

    // ---- load + convert: Q/K direct, V transposed ----
    {
        const int offs[3] = {0, 2 * CDIM, 3 * CDIM};     // k, qA, qB
        const int dh[3]   = {O_KH, O_QAH, O_QBH};
        #pragma unroll
        for (int tt = 0; tt < 3; tt++) {
            #pragma unroll
            for (int rr = 0; rr < 8; rr++) {
                int row = wid * 8 + rr;
                float f = Y[(size_t)(b * NTOK + row) * K4 + offs[tt] + h * HD + lane];
                __nv_bfloat16 hh = __float2bfloat16(f);
                __nv_bfloat16 ll = __float2bfloat16(f - __bfloat162float(hh));
                smh[dh[tt] + row * PQ + lane]        = hh;
                smh[dh[tt] + 2560 + row * PQ + lane] = ll;
            }
        }
        #pragma unroll
        for (int rr = 0; rr < 8; rr++) {
            int j = wid * 8 + rr;
            float f = Y[(size_t)(b * NTOK + j) * K4 + CDIM + h * HD + lane];
            __nv_bfloat16 hh = __float2bfloat16(f);
            __nv_bfloat16 ll = __float2bfloat16(f - __bfloat162float(hh));
            smh[O_VH + lane * PV2 + j] = hh;
            smh[O_VL + lane * PV2 + j] = ll;
        }
    }
    __syncthreads();

    const int type    = wid >> 2;
    const int rowBase = (wid & 3) * 16;
    const float scl   = type ? (z ? SCALE : SCALE * SCALE)
                             : (z ? 1.0f  : SCALE);
    const int  tbl    = type ? (z ? 2 : 3) : (z ? 1 : 0);
    const float* bias = g_bias + (size_t)(tbl * NHEADS + h) * (NTOK * NTOK);

    const unsigned frow = (unsigned)(lane & 15);
    const unsigned fkof = (unsigned)(lane >> 4) * 8;
    const int g = lane >> 2;
    const int q = lane & 3;

    // ---- Q fragments (hi/lo, 2 k-steps) ----
    const unsigned qbase = type ? O_QBH : O_QAH;
    unsigned qh[2][4], ql[2][4];
    #pragma unroll
    for (int ks = 0; ks < 2; ks++) {
        unsigned a = sb + (qbase + (rowBase + frow) * PQ + ks * 16 + fkof) * 2;
        ldsm4(qh[ks], a);
        ldsm4(ql[ks], a + 2560 * 2);
    }

    // ---- QK^T: D[8 n-tiles][4] ----
    float D[8][4];
    #pragma unroll
    for (int i = 0; i < 8; i++)
        #pragma unroll
        for (int j = 0; j < 4; j++) D[i][j] = 0.f;

    #pragma unroll
    for (int ng = 0; ng < 4; ng++) {
        unsigned kh[2][4], kl[2][4];
        #pragma unroll
        for (int ks = 0; ks < 2; ks++) {
            unsigned a = sb + (O_KH + (ng * 16 + frow) * PQ + ks * 16 + fkof) * 2;
            ldsm4(kh[ks], a);
            ldsm4(kl[ks], a + 2560 * 2);
        }
        #pragma unroll
        for (int ks = 0; ks < 2; ks++) {
            #pragma unroll
            for (int na = 0; na < 2; na++) {
                float* d = D[2 * ng + na];
                mma16816(d, qh[ks], kh[ks][na], kh[ks][na + 2]);
                mma16816(d, qh[ks], kl[ks][na], kl[ks][na + 2]);
                mma16816(d, ql[ks], kh[ks][na], kh[ks][na + 2]);
            }
        }
    }

    // ---- scale + bias ----
    #pragma unroll
    for (int nt = 0; nt < 8; nt++) {
        float2 b0 = *(const float2*)&bias[(rowBase + g) * NTOK + nt * 8 + 2 * q];
        float2 b1 = *(const float2*)&bias[(rowBase + g + 8) * NTOK + nt * 8 + 2 * q];
        D[nt][0] = fmaf(scl, D[nt][0], b0.x);
        D[nt][1] = fmaf(scl, D[nt][1], b0.y);
        D[nt][2] = fmaf(scl, D[nt][2], b1.x);
        D[nt][3] = fmaf(scl, D[nt][3], b1.y);
    }

    // ---- row softmax (quad shuffles; rows g and g+8) ----
    float m0 = -1e30f, m1 = -1e30f;
    #pragma unroll
    for (int nt = 0; nt < 8; nt++) {
        m0 = fmaxf(m0, fmaxf(D[nt][0], D[nt][1]));
        m1 = fmaxf(m1, fmaxf(D[nt][2], D[nt][3]));
    }
    m0 = fmaxf(m0, __shfl_xor_sync(0xffffffffu, m0, 1));
    m0 = fmaxf(m0, __shfl_xor_sync(0xffffffffu, m0, 2));
    m1 = fmaxf(m1, __shfl_xor_sync(0xffffffffu, m1, 1));
    m1 = fmaxf(m1, __shfl_xor_sync(0xffffffffu, m1, 2));

    float s0 = 0.f, s1 = 0.f;
    #pragma unroll
    for (int nt = 0; nt < 8; nt++) {
        D[nt][0] = fast_exp(D[nt][0] - m0);
        D[nt][1] = fast_exp(D[nt][1] - m0);
        D[nt][2] = fast_exp(D[nt][2] - m1);
        D[nt][3] = fast_exp(D[nt][3] - m1);
        s0 += D[nt][0] + D[nt][1];
        s1 += D[nt][2] + D[nt][3];
    }
    s0 += __shfl_xor_sync(0xffffffffu, s0, 1);
    s0 += __shfl_xor_sync(0xffffffffu, s0, 2);
    s1 += __shfl_xor_sync(0xffffffffu, s1, 1);
    s1 += __shfl_xor_sync(0xffffffffu, s1, 2);
    const float i0 = 1.f / s0;
    const float i1 = 1.f / s1;

    // ---- P fragments (hi/lo) from D registers; inv folded in ----
    unsigned pah[4][4], pal[4][4];
    #pragma unroll
    for (int kt = 0; kt < 4; kt++) {
        #pragma unroll
        for (int half = 0; half < 2; half++) {       // n-tile 2kt, 2kt+1
            float c0 = D[2 * kt + half][0] * i0;
            float c1 = D[2 * kt + half][1] * i0;
            float c2 = D[2 * kt + half][2] * i1;
            float c3 = D[2 * kt + half][3] * i1;
            __nv_bfloat16 h0 = __float2bfloat16(c0);
            __nv_bfloat16 h1 = __float2bfloat16(c1);
            __nv_bfloat16 h2 = __float2bfloat16(c2);
            __nv_bfloat16 h3 = __float2bfloat16(c3);
            pah[kt][2 * half + 0] = pkbf(__bfloat162float(h0) * 0.f + c0 - (c0 - __bfloat162float(h0)),
                                         __bfloat162float(h1) * 0.f + c1 - (c1 - __bfloat162float(h1)));
            // simpler: re-pack exactly
            __nv_bfloat162 hh01; hh01.x = h0; hh01.y = h1;
            __nv_bfloat162 hh23; hh23.x = h2; hh23.y = h3;
            pah[kt][2 * half + 0] = *(unsigned*)&hh01;
            pah[kt][2 * half + 1] = *(unsigned*)&hh23;
            __nv_bfloat162 ll01;
            ll01.x = __float2bfloat16(c0 - __bfloat162float(h0));
            ll01.y = __float2bfloat16(c1 - __bfloat162float(h1));
            __nv_bfloat162 ll23;
            ll23.x = __float2bfloat16(c2 - __bfloat162float(h2));
            ll23.y = __float2bfloat16(c3 - __bfloat162float(h3));
            pal[kt][2 * half + 0] = *(unsigned*)&ll01;
            pal[kt][2 * half + 1] = *(unsigned*)&ll23;
        }
    }

    // ---- PV: O[4 n-tiles][4] over n=32 dims, k=64 ----
    float O[4][4];
    #pragma unroll
    for (int i = 0; i < 4; i++)
        #pragma unroll
        for (int j = 0; j < 4; j++) O[i][j] = 0.f;

    #pragma unroll
    for (int nv = 0; nv < 2; nv++) {
        #pragma unroll
        for (int kt = 0; kt < 4; kt++) {
            unsigned a = sb + (O_VH + (nv * 16 + frow) * PV2 + kt * 16 + fkof) * 2;
            unsigned vh[4], vl[4];
            ldsm4(vh, a);
            ldsm4(vl, a + (O_VL - O_VH) * 2);
            #pragma unroll
            for (int na = 0; na < 2; na++) {
                float* d = O[2 * nv + na];
                mma16816(d, pah[kt], vh[na], vh[na + 2]);
                mma16816(d, pah[kt], vl[na], vl[na + 2]);
                mma16816(d, pal[kt], vh[na], vh[na + 2]);
            }
        }
    }

    // ---- epilogue: bf16 hi/lo row-major stores into merge buffers ----
    __nv_bfloat16* oHi = type ? g_Mh_hi : g_Mv_hi;
    __nv_bfloat16* oLo = type ? g_Mh_lo : g_Mv_lo;
    const int colb = (type ? (z ? 0 : CDIM) : (z ? CDIM : 0)) + h * HD;

    #pragma unroll
    for (int nt = 0; nt < 4; nt++) {
        int col = colb + nt * 8 + 2 * q;
        #pragma unroll
        for (int half = 0; half < 2; half++) {
            int row = b * NTOK + rowBase + g + 8 * half;
            float v0 = O[nt][2 * half + 0];
            float v1 = O[nt][2 * half + 1];
            __nv_bfloat16 h0 = __float2bfloat16(v0);
            __nv_bfloat16 h1 = __float2bfloat16(v1);
            __nv_bfloat162 hh; hh.x = h0; hh.y = h1;
            __nv_bfloat162 ll;
            ll.x = __float2bfloat16(v0 - __bfloat162float(h0));
            ll.y = __float2bfloat16(v1 - __bfloat162float(h1));
            *(unsigned*)&oHi[(size_t)row * (2 * CDIM) + col] = *(unsigned*)&hh;
            *(unsigned*)&oLo[(size_t)row * (2 * CDIM) + col] = *(unsigned*)&ll;
        }
    }
}

// ---------------------------------------------------------------------------
// Stage-3 tensor GEMM (HMMA): C[M,96] = M[token,192] @ W[96,192]^T + bias.
// ---------------------------------------------------------------------------
#define PB2   200
#define AROW2 (PB2 * 2)
#define S3_AH 0
#define S3_AL (128 * AROW2)
#define S3_BH (2 * 128 * AROW2)
#define S3_BL (S3_BH + CDIM * AROW2)
#define S3_SMEM (S3_BL + CDIM * AROW2)

__global__ __launch_bounds__(256)
void mma_gemm3(const float* __restrict__ bpv, const float* __restrict__ bph,
               float* __restrict__ out, float* __restrict__ state)
{
    extern __shared__ char smc[];
    const unsigned sb = (unsigned)__cvta_generic_to_shared(smc);

    const int t    = threadIdx.x;
    const int lane = t & 31;
    const int wid  = t >> 5;
    const int mBase = blockIdx.x * 128;
    const int z     = blockIdx.z;

    const __nv_bfloat16* Ah = z ? g_Mh_hi : g_Mv_hi;
    const __nv_bfloat16* Al = z ? g_Mh_lo : g_Mv_lo;
    const __nv_bfloat16* Bh = z ? g_Wph_hi : g_Wpv_hi;
    const __nv_bfloat16* Bl = z ? g_Wph_lo : g_Wpv_lo;
    const float* bias = z ? bph : bpv;
    float* C = z ? state : out;

    {
        const __nv_bfloat16* aH = Ah + (size_t)mBase * (2 * CDIM);
        const __nv_bfloat16* aL = Al + (size_t)mBase * (2 * CDIM);
        #pragma unroll
        for (int it = 0; it < 12; it++) {
            int g   = t + 256 * it;
            int row = g / 24;
            int gr  = g % 24;
            cpa16(sb + S3_AH + row * AROW2 + gr * 16, aH + row * (2 * CDIM) + gr * 8);
            cpa16(sb + S3_AL + row * AROW2 + gr * 16, aL + row * (2 * CDIM) + gr * 8);
        }
        #pragma unroll
        for (int it = 0; it < 9; it++) {
            int g = t + 256 * it;
            int row = g / 24;
            int gr  = g % 24;
            cpa16(sb + S3_BH + row * AROW2 + gr * 16, Bh + row * (2 * CDIM) + gr * 8);
            cpa16(sb + S3_BL + row * AROW2 + gr * 16, Bl + row * (2 * CDIM) + gr * 8);
        }
        cpa_commit();
        asm volatile("cp.async.wait_group 0;");
    }
    __syncthreads();

    const int mW = (wid & 3) * 32;
    const int nW = (wid >> 2) * 48;

    float D[12][4];
    #pragma unroll
    for (int i = 0; i < 12; i++)
        #pragma unroll
        for (int j = 0; j < 4; j++) D[i][j] = 0.f;

    const unsigned frow = (unsigned)(lane & 15);
    const unsigned fkof = (unsigned)(lane >> 4) * 8;

    #pragma unroll
    for (int s = 0; s < 12; s++) {
        const unsigned k0 = s * 16;
        unsigned ah[2][4], al[2][4];
        #pragma unroll
        for (int m = 0; m < 2; m++) {
            unsigned off = ((mW + m * 16 + frow) * PB2 + k0 + fkof) * 2;
            ldsm4(ah[m], sb + S3_AH + off);
            ldsm4(al[m], sb + S3_AL + off);
        }
        #pragma unroll
        for (int p = 0; p < 3; p++) {
            unsigned boff = ((nW + p * 16 + frow) * PB2 + k0 + fkof) * 2;
            unsigned bh[4], bl[4];
            ldsm4(bh, sb + S3_BH + boff);
            ldsm4(bl, sb + S3_BL + boff);
            #pragma unroll
            for (int m = 0; m < 2; m++) {
                #pragma unroll
                for (int na = 0; na < 2; na++) {
                    float* d = D[m * 6 + p * 2 + na];
                    mma16816(d, ah[m], bh[na], bh[na + 2]);
                    mma16816(d, ah[m], bl[na], bl[na + 2]);
                    mma16816(d, al[m], bh[na], bh[na + 2]);
                }
            }
        }
    }

    #pragma unroll
    for (int m = 0; m < 2; m++) {
        int rA = mBase + mW + m * 16 + (lane >> 2);
        #pragma unroll
        for (int n = 0; n < 6; n++) {
            int col = nW + n * 8 + (lane & 3) * 2;
            float2 bv = *(const float2*)&bias[col];
            float* d = D[m * 6 + n];
            float2 r0; r0.x = d[0] + bv.x; r0.y = d[1] + bv.y;
            float2 r1; r1.x = d[2] + bv.x; r1.y = d[3] + bv.y;
            *(float2*)&C[(size_t)rA * CDIM + col]       = r0;
            *(float2*)&C[(size_t)(rA + 8) * CDIM + col] = r1;
        }
    }
}

// ---------------------------------------------------------------------------
// Launch
// ---------------------------------------------------------------------------
extern "C" void kernel_launch(void* const* d_in, const int* in_sizes, int n_in,
                              void* d_out, int out_size)
{
    const float* input_x = (const float*)d_in[0];
    const float* state_x = (const float*)d_in[1];
    const float* Ws      = (const float*)d_in[2];
    const float* bs      = (const float*)d_in[3];
    const float* We      = (const float*)d_in[4];
    const float* be      = (const float*)d_in[5];
    const float* tcv     = (const float*)d_in[6];
    const float* tsv     = (const float*)d_in[7];
    const float* tch     = (const float*)d_in[8];
    const float* tsh     = (const float*)d_in[9];
    const float* Wpv     = (const float*)d_in[10];
    const float* bpv     = (const float*)d_in[11];
    const float* Wph     = (const float*)d_in[12];
    const float* bph     = (const float*)d_in[13];
    const int*   rel_idx = (const int*)d_in[14];

    float* out   = (float*)d_out;
    float* state = out + (size_t)MTOK * CDIM;

    __nv_bfloat16 *pXsH, *pXsL, *pXeH, *pXeL, *pWsH, *pWsL, *pWeH, *pWeL;
    __nv_bfloat16 *pWpvH, *pWpvL, *pWphH, *pWphL;
    float *pYs, *pYe;
    cudaGetSymbolAddress((void**)&pXsH, g_Xs_hi);
    cudaGetSymbolAddress((void**)&pXsL, g_Xs_lo);
    cudaGetSymbolAddress((void**)&pXeH, g_Xe_hi);
    cudaGetSymbolAddress((void**)&pXeL, g_Xe_lo);
    cudaGetSymbolAddress((void**)&pWsH, g_Ws_hi);
    cudaGetSymbolAddress((void**)&pWsL, g_Ws_lo);
    cudaGetSymbolAddress((void**)&pWeH, g_We_hi);
    cudaGetSymbolAddress((void**)&pWeL, g_We_lo);
    cudaGetSymbolAddress((void**)&pWpvH, g_Wpv_hi);
    cudaGetSymbolAddress((void**)&pWpvL, g_Wpv_lo);
    cudaGetSymbolAddress((void**)&pWphH, g_Wph_hi);
    cudaGetSymbolAddress((void**)&pWphL, g_Wph_lo);
    cudaGetSymbolAddress((void**)&pYs,  g_Ys);
    cudaGetSymbolAddress((void**)&pYe,  g_Ye);

    cudaFuncSetAttribute(mma_gemm,
                         cudaFuncAttributeMaxDynamicSharedMemorySize, MMA_SMEM);
    cudaFuncSetAttribute(mma_gemm3,
                         cudaFuncAttributeMaxDynamicSharedMemorySize, S3_SMEM);

    // Prepass: converts + bias gather
    {
        size_t nX = (size_t)MTOK * CDIM;
        convert_split<<<(unsigned)((nX / 4 + 255) / 256), 256>>>(state_x, pXsH, pXsL, nX);
        convert_split<<<(unsigned)((nX / 4 + 255) / 256), 256>>>(input_x, pXeH, pXeL, nX);
        size_t nW = (size_t)K4 * CDIM;
        convert_split<<<(unsigned)((nW / 4 + 255) / 256), 256>>>(Ws, pWsH, pWsL, nW);
        convert_split<<<(unsigned)((nW / 4 + 255) / 256), 256>>>(We, pWeH, pWeL, nW);
        size_t nP = (size_t)CDIM * 2 * CDIM;
        convert_split<<<(unsigned)((nP / 4 + 255) / 256), 256>>>(Wpv, pWpvH, pWpvL, nP);
        convert_split<<<(unsigned)((nP / 4 + 255) / 256), 256>>>(Wph, pWphH, pWphL, nP);
        dim3 gb(NTOK * NTOK / 256, 4, NHEADS);
        bias_gather<<<gb, 256>>>(tcv, tsv, tch, tsh, rel_idx);
    }

    // Stage 1: projections on HMMA
    {
        dim3 grid(MTOK / 128, K4 / 128, 2);
        mma_gemm<<<grid, 256, MMA_SMEM>>>(pXsH, pXsL, pXeH, pXeL,
                                          pWsH, pWsL, pWeH, pWeL,
                                          bs, be, pYs, pYe);
    }

    // Stage 2: window attention on HMMA -> bf16 hi/lo merge buffers
    {
        dim3 grid(BATCH, NHEADS, 2);
        attn_mma<<<grid, 256>>>();
    }

    // Stage 3: output projections on HMMA
    {
        dim3 grid(MTOK / 128, 1, 2);
        mma_gemm3<<<grid, 256, S3_SMEM>>>(bpv, bph, out, state);
    }
}